// round 1
// baseline (speedup 1.0000x reference)
#include <cuda_runtime.h>

#define Nn   40000
#define Ee   640000
#define INF  128
#define HIDF 256
#define CLSF 40

// ---- scratch (device globals; no allocation allowed) ----
__device__ int    g_deg[Nn];
__device__ int    g_row[Nn + 1];
__device__ int    g_cur[Nn];
__device__ int    g_esrc[Ee];
__device__ float  g_norm[Nn];
__device__ float  g_norm2[Nn];
__device__ float4 g_buf0[Nn * (INF / 4)];   // A(m.X)
__device__ float4 g_buf1[Nn * (INF / 4)];   // A(m^2 . buf0)
__device__ float4 g_z[Nn * (HIDF / 4)];     // relu(h@W1+b1)

// ---------------- degree / CSR build ----------------
__global__ void zero_deg_k() {
    int i = blockIdx.x * blockDim.x + threadIdx.x;
    if (i < Nn) g_deg[i] = 0;
}

__global__ void hist_k(const int* __restrict__ dst) {
    int i = blockIdx.x * blockDim.x + threadIdx.x;
    if (i < Ee) atomicAdd(&g_deg[dst[i]], 1);
}

// single block: exclusive scan of deg -> row/cur, plus norm tables
__global__ void scan_k() {
    __shared__ int sums[1024];
    const int IPT = (Nn + 1023) / 1024;   // 40
    int t = threadIdx.x;
    int base = t * IPT;
    int s = 0;
    for (int i = 0; i < IPT; i++) {
        int idx = base + i;
        if (idx < Nn) s += g_deg[idx];
    }
    sums[t] = s;
    __syncthreads();
    for (int off = 1; off < 1024; off <<= 1) {
        int v = (t >= off) ? sums[t - off] : 0;
        __syncthreads();
        sums[t] += v;
        __syncthreads();
    }
    int run = (t > 0) ? sums[t - 1] : 0;
    for (int i = 0; i < IPT; i++) {
        int idx = base + i;
        if (idx < Nn) {
            g_row[idx] = run;
            g_cur[idx] = run;
            int d = g_deg[idx];
            run += d;
            float nm = rsqrtf(fmaxf((float)d, 1.0f));
            g_norm[idx]  = nm;
            g_norm2[idx] = nm * nm;
        }
    }
    if (t == 1023) g_row[Nn] = sums[1023];
}

__global__ void permute_k(const int* __restrict__ src, const int* __restrict__ dst) {
    int i = blockIdx.x * blockDim.x + threadIdx.x;
    if (i < Ee) {
        int d = dst[i];
        int p = atomicAdd(&g_cur[d], 1);
        g_esrc[p] = src[i];
    }
}

// ---------------- propagation: warp-per-node gather-sum ----------------
// hop==1: buf0[v] = sum_{e->v} norm[src] * X[src]
// hop==2: buf1[v] = sum_{e->v} norm2[src] * buf0[src]
__global__ void gather_k(const float4* __restrict__ xin, int hop) {
    int w    = (blockIdx.x * blockDim.x + threadIdx.x) >> 5;
    int lane = threadIdx.x & 31;
    if (w >= Nn) return;
    const float4* hin = (hop == 1) ? xin : (const float4*)g_buf0;
    const float*  m   = (hop == 1) ? g_norm : g_norm2;
    float4*       hout = (hop == 1) ? g_buf0 : g_buf1;

    int beg = g_row[w];
    int end = beg + g_deg[w];
    float ax = 0.f, ay = 0.f, az = 0.f, aw = 0.f;
    int e = beg;
    for (; e + 1 < end; e += 2) {
        int s0 = g_esrc[e];
        int s1 = g_esrc[e + 1];
        float w0 = m[s0];
        float w1 = m[s1];
        float4 x0 = hin[s0 * 32 + lane];
        float4 x1 = hin[s1 * 32 + lane];
        ax += w0 * x0.x + w1 * x1.x;
        ay += w0 * x0.y + w1 * x1.y;
        az += w0 * x0.z + w1 * x1.z;
        aw += w0 * x0.w + w1 * x1.w;
    }
    if (e < end) {
        int s0 = g_esrc[e];
        float w0 = m[s0];
        float4 x0 = hin[s0 * 32 + lane];
        ax += w0 * x0.x;
        ay += w0 * x0.y;
        az += w0 * x0.z;
        aw += w0 * x0.w;
    }
    hout[w * 32 + lane] = make_float4(ax, ay, az, aw);
}

// ---------------- GEMM1: z = relu( (norm .* buf1) @ W1 + b1 ) ----------------
// 64x64 tile, K chunked by 64, 256 threads, 4x4 micro-tile
__global__ void gemm1_k(const float* __restrict__ W1, const float* __restrict__ b1) {
    __shared__ float As[64][68];   // [m][k], padded row (272B, 16B aligned)
    __shared__ float Bs[64][64];   // [k][n]
    int tid = threadIdx.x;
    int tx  = tid & 15;
    int ty  = tid >> 4;
    int m0  = blockIdx.x * 64;
    int n0  = blockIdx.y * 64;
    const float* bufA = (const float*)g_buf1;

    float acc[16];
#pragma unroll
    for (int i = 0; i < 16; i++) acc[i] = 0.f;

    for (int kc = 0; kc < INF; kc += 64) {
#pragma unroll
        for (int i = 0; i < 4; i++) {
            int id = tid + i * 256;        // 0..1023
            int mm = id >> 4;              // 0..63
            int k4 = id & 15;              // 0..15
            float nm = g_norm[m0 + mm];
            float4 v = *(const float4*)&bufA[(m0 + mm) * INF + kc + k4 * 4];
            *(float4*)&As[mm][k4 * 4] =
                make_float4(v.x * nm, v.y * nm, v.z * nm, v.w * nm);
        }
#pragma unroll
        for (int i = 0; i < 4; i++) {
            int id = tid + i * 256;
            int kk = id >> 4;
            int n4 = id & 15;
            *(float4*)&Bs[kk][n4 * 4] =
                *(const float4*)&W1[(kc + kk) * HIDF + n0 + n4 * 4];
        }
        __syncthreads();
#pragma unroll
        for (int k = 0; k < 64; k++) {
            float4 bv = *(const float4*)&Bs[k][tx * 4];
#pragma unroll
            for (int i = 0; i < 4; i++) {
                float a = As[ty * 4 + i][k];
                acc[i * 4 + 0] += a * bv.x;
                acc[i * 4 + 1] += a * bv.y;
                acc[i * 4 + 2] += a * bv.z;
                acc[i * 4 + 3] += a * bv.w;
            }
        }
        __syncthreads();
    }

    float4 bb = *(const float4*)&b1[n0 + tx * 4];
    float* zf = (float*)g_z;
#pragma unroll
    for (int i = 0; i < 4; i++) {
        int m = m0 + ty * 4 + i;
        float4 r;
        r.x = fmaxf(acc[i * 4 + 0] + bb.x, 0.f);
        r.y = fmaxf(acc[i * 4 + 1] + bb.y, 0.f);
        r.z = fmaxf(acc[i * 4 + 2] + bb.z, 0.f);
        r.w = fmaxf(acc[i * 4 + 3] + bb.w, 0.f);
        *(float4*)&zf[m * HIDF + n0 + tx * 4] = r;
    }
}

// ---------------- GEMM2: out = z @ W2 + b2 ----------------
// thread-per-row, W2 staged in 32-row chunks, broadcast reads
__global__ void gemm2_k(const float* __restrict__ W2, const float* __restrict__ b2,
                        float* __restrict__ out) {
    __shared__ float W2s[32][CLSF];
    int tid = threadIdx.x;
    int row = blockIdx.x * 128 + tid;

    float acc[CLSF];
#pragma unroll
    for (int c = 0; c < CLSF; c++) acc[c] = 0.f;

    const float* zf = (const float*)g_z;

    for (int kc = 0; kc < HIDF; kc += 32) {
        for (int i = tid; i < 32 * CLSF; i += 128) {
            int r = i / CLSF;
            int c = i % CLSF;
            W2s[r][c] = W2[(kc + r) * CLSF + c];
        }
        __syncthreads();
        if (row < Nn) {
            const float4* zr = (const float4*)&zf[row * HIDF + kc];
#pragma unroll
            for (int j = 0; j < 8; j++) {
                float4 z4 = zr[j];
                float zz[4] = {z4.x, z4.y, z4.z, z4.w};
#pragma unroll
                for (int q = 0; q < 4; q++) {
                    float zv = zz[q];
                    int k = j * 4 + q;
#pragma unroll
                    for (int c4 = 0; c4 < CLSF / 4; c4++) {
                        float4 wv = *(const float4*)&W2s[k][c4 * 4];
                        acc[c4 * 4 + 0] += zv * wv.x;
                        acc[c4 * 4 + 1] += zv * wv.y;
                        acc[c4 * 4 + 2] += zv * wv.z;
                        acc[c4 * 4 + 3] += zv * wv.w;
                    }
                }
            }
        }
        __syncthreads();
    }

    if (row < Nn) {
#pragma unroll
        for (int c = 0; c < CLSF; c++) out[row * CLSF + c] = acc[c] + b2[c];
    }
}

extern "C" void kernel_launch(void* const* d_in, const int* in_sizes, int n_in,
                              void* d_out, int out_size) {
    const float* features = (const float*)d_in[0];
    const int*   src      = (const int*)d_in[1];
    const int*   dst      = (const int*)d_in[2];
    const float* W1       = (const float*)d_in[3];
    const float* b1       = (const float*)d_in[4];
    const float* W2       = (const float*)d_in[5];
    const float* b2       = (const float*)d_in[6];
    float*       out      = (float*)d_out;

    zero_deg_k<<<(Nn + 255) / 256, 256>>>();
    hist_k<<<(Ee + 255) / 256, 256>>>(dst);
    scan_k<<<1, 1024>>>();
    permute_k<<<(Ee + 255) / 256, 256>>>(src, dst);

    // hop 1: buf0 = A (norm . X)
    gather_k<<<Nn / 8, 256>>>((const float4*)features, 1);
    // hop 2: buf1 = A (norm^2 . buf0)
    gather_k<<<Nn / 8, 256>>>((const float4*)features, 2);

    gemm1_k<<<dim3(Nn / 64, HIDF / 64), 256>>>(W1, b1);
    gemm2_k<<<(Nn + 127) / 128, 128>>>(W2, b2, out);
}

// round 7
// speedup vs baseline: 1.0333x; 1.0333x over previous
#include <cuda_runtime.h>
#include <cuda_bf16.h>
#include <cstdint>

#define Nn   40000
#define Ee   640000
#define INF  128
#define HIDF 256
#define CLSF 40
#define MTILES 313
#define MPAD  (MTILES * 128)     // 40064

// ---- scratch (device globals; zero-initialized at load) ----
__device__ int    g_deg[Nn];
__device__ int    g_row[Nn + 1];
__device__ int    g_cur[Nn];
__device__ int    g_esrc[Ee];
__device__ float  g_norm[MPAD];          // pad rows stay 0
__device__ float  g_norm2[Nn];
__device__ float4 g_buf0[Nn * (INF / 4)];
__device__ float4 g_buf1[MPAD * (INF / 4)];       // pad rows stay 0
__device__ __align__(16) unsigned short g_Bhi[HIDF * INF];  // W1^T bf16 hi, [n][k]
__device__ __align__(16) unsigned short g_Blo[HIDF * INF];  // W1^T bf16 lo
__device__ float4 g_z[Nn * (HIDF / 4)];

// ---------------- degree / CSR build ----------------
__global__ void zero_deg_k() {
    int i = blockIdx.x * blockDim.x + threadIdx.x;
    if (i < Nn) g_deg[i] = 0;
}
__global__ void hist_k(const int* __restrict__ dst) {
    int i = blockIdx.x * blockDim.x + threadIdx.x;
    if (i < Ee) atomicAdd(&g_deg[dst[i]], 1);
}
__global__ void scan_k() {
    __shared__ int sums[1024];
    const int IPT = (Nn + 1023) / 1024;
    int t = threadIdx.x, base = t * IPT, s = 0;
    for (int i = 0; i < IPT; i++) { int idx = base + i; if (idx < Nn) s += g_deg[idx]; }
    sums[t] = s;
    __syncthreads();
    for (int off = 1; off < 1024; off <<= 1) {
        int v = (t >= off) ? sums[t - off] : 0;
        __syncthreads(); sums[t] += v; __syncthreads();
    }
    int run = (t > 0) ? sums[t - 1] : 0;
    for (int i = 0; i < IPT; i++) {
        int idx = base + i;
        if (idx < Nn) {
            g_row[idx] = run; g_cur[idx] = run;
            int d = g_deg[idx]; run += d;
            float nm = rsqrtf(fmaxf((float)d, 1.0f));
            g_norm[idx] = nm; g_norm2[idx] = nm * nm;
        }
    }
    if (t == 1023) g_row[Nn] = sums[1023];
}
__global__ void permute_k(const int* __restrict__ src, const int* __restrict__ dst) {
    int i = blockIdx.x * blockDim.x + threadIdx.x;
    if (i < Ee) { int d = dst[i]; int p = atomicAdd(&g_cur[d], 1); g_esrc[p] = src[i]; }
}

// ---------------- propagation (warp-per-node gather) ----------------
__global__ void gather1_k(const float4* __restrict__ xin) {
    int w = (blockIdx.x * blockDim.x + threadIdx.x) >> 5;
    int lane = threadIdx.x & 31;
    if (w >= Nn) return;
    int beg = g_row[w], end = beg + g_deg[w];
    float ax = 0.f, ay = 0.f, az = 0.f, aw = 0.f;
    int e = beg;
    for (; e + 1 < end; e += 2) {
        int s0 = g_esrc[e], s1 = g_esrc[e + 1];
        float w0 = g_norm[s0], w1 = g_norm[s1];
        float4 x0 = xin[s0 * 32 + lane], x1 = xin[s1 * 32 + lane];
        ax += w0 * x0.x + w1 * x1.x; ay += w0 * x0.y + w1 * x1.y;
        az += w0 * x0.z + w1 * x1.z; aw += w0 * x0.w + w1 * x1.w;
    }
    if (e < end) {
        int s0 = g_esrc[e]; float w0 = g_norm[s0];
        float4 x0 = xin[s0 * 32 + lane];
        ax += w0 * x0.x; ay += w0 * x0.y; az += w0 * x0.z; aw += w0 * x0.w;
    }
    g_buf0[w * 32 + lane] = make_float4(ax, ay, az, aw);
}

__global__ void gather2_k() {
    int w = (blockIdx.x * blockDim.x + threadIdx.x) >> 5;
    int lane = threadIdx.x & 31;
    if (w >= Nn) return;
    int beg = g_row[w], end = beg + g_deg[w];
    float ax = 0.f, ay = 0.f, az = 0.f, aw = 0.f;
    int e = beg;
    for (; e + 1 < end; e += 2) {
        int s0 = g_esrc[e], s1 = g_esrc[e + 1];
        float w0 = g_norm2[s0], w1 = g_norm2[s1];
        float4 x0 = g_buf0[s0 * 32 + lane], x1 = g_buf0[s1 * 32 + lane];
        ax += w0 * x0.x + w1 * x1.x; ay += w0 * x0.y + w1 * x1.y;
        az += w0 * x0.z + w1 * x1.z; aw += w0 * x0.w + w1 * x1.w;
    }
    if (e < end) {
        int s0 = g_esrc[e]; float w0 = g_norm2[s0];
        float4 x0 = g_buf0[s0 * 32 + lane];
        ax += w0 * x0.x; ay += w0 * x0.y; az += w0 * x0.z; aw += w0 * x0.w;
    }
    g_buf1[w * 32 + lane] = make_float4(ax, ay, az, aw);
}

// ---- W1 prep: g_B{hi,lo}[n][k] = split-bf16 of W1[k][n] ----
__global__ void prepW1_k(const float* __restrict__ W1) {
    int t = blockIdx.x * blockDim.x + threadIdx.x;   // 8192 threads
    int n = t >> 5, k0 = (t & 31) * 4;
    unsigned short hi[4], lo[4];
#pragma unroll
    for (int i = 0; i < 4; i++) {
        float v = W1[(k0 + i) * HIDF + n];
        __nv_bfloat16 h = __float2bfloat16(v);
        float hf = __bfloat162float(h);
        __nv_bfloat16 l = __float2bfloat16(v - hf);
        hi[i] = __bfloat16_as_ushort(h);
        lo[i] = __bfloat16_as_ushort(l);
    }
    *(uint2*)&g_Bhi[n * INF + k0] =
        make_uint2((uint32_t)hi[1] << 16 | hi[0], (uint32_t)hi[3] << 16 | hi[2]);
    *(uint2*)&g_Blo[n * INF + k0] =
        make_uint2((uint32_t)lo[1] << 16 | lo[0], (uint32_t)lo[3] << 16 | lo[2]);
}

// ---------------- GEMM1 via mma.sync bf16 split (hh+hl+lh) ----------------
#define LDAB 136                 // smem row stride in bf16 elems (272 B)
#define SA_H 0
#define SA_L 34816
#define SB_H 69632
#define SB_L 104448
#define SM_TOT 139264

__device__ __forceinline__ uint32_t smem_u32(const void* p) {
    uint32_t a;
    asm("{ .reg .u64 t; cvta.to.shared.u64 t, %1; cvt.u32.u64 %0, t; }" : "=r"(a) : "l"(p));
    return a;
}
#define LDSM4(R, addr) \
    asm volatile("ldmatrix.sync.aligned.m8n8.x4.shared.b16 {%0,%1,%2,%3}, [%4];" \
        : "=r"((R)[0]), "=r"((R)[1]), "=r"((R)[2]), "=r"((R)[3]) : "r"(addr))
#define MMA16816(C, A, B0, B1) \
    asm volatile("mma.sync.aligned.m16n8k16.row.col.f32.bf16.bf16.f32 " \
        "{%0,%1,%2,%3},{%4,%5,%6,%7},{%8,%9},{%0,%1,%2,%3};" \
        : "+f"((C)[0]), "+f"((C)[1]), "+f"((C)[2]), "+f"((C)[3]) \
        : "r"((A)[0]), "r"((A)[1]), "r"((A)[2]), "r"((A)[3]), "r"(B0), "r"(B1))

__global__ void __launch_bounds__(256, 1) gemm1_mma(const float* __restrict__ b1) {
    extern __shared__ char sm[];
    int tid = threadIdx.x;
    int m0 = blockIdx.x * 128, n0 = blockIdx.y * 128;

    // ---- fill A (hi/lo split, norm folded in) ----
    {
        int mm = tid >> 1, kh = tid & 1;
        float nm = g_norm[m0 + mm];
        const float4* srow = g_buf1 + (size_t)(m0 + mm) * 32 + kh * 16;
        unsigned short* dh = (unsigned short*)(sm + SA_H) + mm * LDAB + kh * 64;
        unsigned short* dl = (unsigned short*)(sm + SA_L) + mm * LDAB + kh * 64;
#pragma unroll
        for (int i = 0; i < 16; i++) {
            float4 v = srow[i];
            float f[4] = {v.x * nm, v.y * nm, v.z * nm, v.w * nm};
            unsigned short hi[4], lo[4];
#pragma unroll
            for (int j = 0; j < 4; j++) {
                __nv_bfloat16 h = __float2bfloat16(f[j]);
                float hf = __bfloat162float(h);
                __nv_bfloat16 l = __float2bfloat16(f[j] - hf);
                hi[j] = __bfloat16_as_ushort(h);
                lo[j] = __bfloat16_as_ushort(l);
            }
            *(uint2*)(dh + i * 4) =
                make_uint2((uint32_t)hi[1] << 16 | hi[0], (uint32_t)hi[3] << 16 | hi[2]);
            *(uint2*)(dl + i * 4) =
                make_uint2((uint32_t)lo[1] << 16 | lo[0], (uint32_t)lo[3] << 16 | lo[2]);
        }
    }
    // ---- copy B tiles (pre-split, transposed) ----
    {
        int nn = tid >> 1, half = tid & 1;
        const uint4* shh = (const uint4*)&g_Bhi[(n0 + nn) * INF + half * 64];
        const uint4* sll = (const uint4*)&g_Blo[(n0 + nn) * INF + half * 64];
        uint4* dh = (uint4*)((unsigned short*)(sm + SB_H) + nn * LDAB + half * 64);
        uint4* dl = (uint4*)((unsigned short*)(sm + SB_L) + nn * LDAB + half * 64);
#pragma unroll
        for (int i = 0; i < 8; i++) { dh[i] = shh[i]; dl[i] = sll[i]; }
    }
    __syncthreads();

    int lane = tid & 31, w = tid >> 5;
    int wm = (w & 3) * 32, wn = (w >> 2) * 64;
    uint32_t sb = smem_u32(sm);

    // ldmatrix base addresses (byte offsets; +k0*2 per k-step)
    uint32_t aRow = (uint32_t)(wm + (lane & 15));
    uint32_t aK   = (uint32_t)((lane >> 4) * 8);
    uint32_t aOffH = sb + SA_H + aRow * 272 + aK * 2;
    uint32_t aOffL = sb + SA_L + aRow * 272 + aK * 2;
    uint32_t bRow = (uint32_t)(wn + (lane & 7) + ((lane >> 4) & 1) * 8);
    uint32_t bK   = (uint32_t)(((lane >> 3) & 1) * 8);
    uint32_t bOffH = sb + SB_H + bRow * 272 + bK * 2;
    uint32_t bOffL = sb + SB_L + bRow * 272 + bK * 2;

    float acc[2][8][4];
#pragma unroll
    for (int a = 0; a < 2; a++)
#pragma unroll
        for (int b = 0; b < 8; b++)
#pragma unroll
            for (int c = 0; c < 4; c++) acc[a][b][c] = 0.f;

#pragma unroll
    for (int ks = 0; ks < 8; ks++) {
        uint32_t k2 = (uint32_t)(ks * 32);   // k0*2 bytes
        uint32_t Ah[2][4], Al[2][4], Bh[4][4], Bl[4][4];
        LDSM4(Ah[0], aOffH + k2);
        LDSM4(Ah[1], aOffH + k2 + 16 * 272);
        LDSM4(Al[0], aOffL + k2);
        LDSM4(Al[1], aOffL + k2 + 16 * 272);
#pragma unroll
        for (int p = 0; p < 4; p++) {
            LDSM4(Bh[p], bOffH + k2 + p * 16 * 272);
            LDSM4(Bl[p], bOffL + k2 + p * 16 * 272);
        }
#pragma unroll
        for (int mf = 0; mf < 2; mf++) {
#pragma unroll
            for (int nf = 0; nf < 8; nf++) {
                int p = nf >> 1, s = (nf & 1) * 2;
                MMA16816(acc[mf][nf], Ah[mf], Bh[p][s], Bh[p][s + 1]);   // hh
                MMA16816(acc[mf][nf], Ah[mf], Bl[p][s], Bl[p][s + 1]);   // hl
                MMA16816(acc[mf][nf], Al[mf], Bh[p][s], Bh[p][s + 1]);   // lh
            }
        }
    }

    // ---- epilogue: z = relu(acc + b1) ----
    int g = lane >> 2, t = lane & 3;
    float* zf = (float*)g_z;
#pragma unroll
    for (int mf = 0; mf < 2; mf++) {
        int r0 = m0 + wm + mf * 16 + g;
        int r1 = r0 + 8;
#pragma unroll
        for (int nf = 0; nf < 8; nf++) {
            int col = n0 + wn + nf * 8 + t * 2;
            float2 bb = *(const float2*)&b1[col];
            if (r0 < Nn) {
                float2 o;
                o.x = fmaxf(acc[mf][nf][0] + bb.x, 0.f);
                o.y = fmaxf(acc[mf][nf][1] + bb.y, 0.f);
                *(float2*)&zf[(size_t)r0 * HIDF + col] = o;
            }
            if (r1 < Nn) {
                float2 o;
                o.x = fmaxf(acc[mf][nf][2] + bb.x, 0.f);
                o.y = fmaxf(acc[mf][nf][3] + bb.y, 0.f);
                *(float2*)&zf[(size_t)r1 * HIDF + col] = o;
            }
        }
    }
}

// ---------------- GEMM2: out = z @ W2 + b2 ----------------
__global__ void gemm2_k(const float* __restrict__ W2, const float* __restrict__ b2,
                        float* __restrict__ out) {
    __shared__ float W2s[32][CLSF];
    int tid = threadIdx.x;
    int row = blockIdx.x * 128 + tid;
    float acc[CLSF];
#pragma unroll
    for (int c = 0; c < CLSF; c++) acc[c] = 0.f;
    const float* zf = (const float*)g_z;
    for (int kc = 0; kc < HIDF; kc += 32) {
        for (int i = tid; i < 32 * CLSF; i += 128) {
            int r = i / CLSF, c = i % CLSF;
            W2s[r][c] = W2[(kc + r) * CLSF + c];
        }
        __syncthreads();
        if (row < Nn) {
            const float4* zr = (const float4*)&zf[(size_t)row * HIDF + kc];
#pragma unroll
            for (int j = 0; j < 8; j++) {
                float4 z4 = zr[j];
                float zz[4] = {z4.x, z4.y, z4.z, z4.w};
#pragma unroll
                for (int q = 0; q < 4; q++) {
                    float zv = zz[q];
                    int k = j * 4 + q;
#pragma unroll
                    for (int c4 = 0; c4 < CLSF / 4; c4++) {
                        float4 wv = *(const float4*)&W2s[k][c4 * 4];
                        acc[c4 * 4 + 0] += zv * wv.x;
                        acc[c4 * 4 + 1] += zv * wv.y;
                        acc[c4 * 4 + 2] += zv * wv.z;
                        acc[c4 * 4 + 3] += zv * wv.w;
                    }
                }
            }
        }
        __syncthreads();
    }
    if (row < Nn) {
#pragma unroll
        for (int c = 0; c < CLSF; c++) out[row * CLSF + c] = acc[c] + b2[c];
    }
}

extern "C" void kernel_launch(void* const* d_in, const int* in_sizes, int n_in,
                              void* d_out, int out_size) {
    const float* features = (const float*)d_in[0];
    const int*   src      = (const int*)d_in[1];
    const int*   dst      = (const int*)d_in[2];
    const float* W1       = (const float*)d_in[3];
    const float* b1       = (const float*)d_in[4];
    const float* W2       = (const float*)d_in[5];
    const float* b2       = (const float*)d_in[6];
    float*       out      = (float*)d_out;

    cudaFuncSetAttribute(gemm1_mma, cudaFuncAttributeMaxDynamicSharedMemorySize, SM_TOT);

    zero_deg_k<<<(Nn + 255) / 256, 256>>>();
    hist_k<<<(Ee + 255) / 256, 256>>>(dst);
    prepW1_k<<<32, 256>>>(W1);
    scan_k<<<1, 1024>>>();
    permute_k<<<(Ee + 255) / 256, 256>>>(src, dst);

    gather1_k<<<Nn / 8, 256>>>((const float4*)features);
    gather2_k<<<Nn / 8, 256>>>();

    gemm1_mma<<<dim3(MTILES, 2), 256, SM_TOT>>>(b1);
    gemm2_k<<<(Nn + 127) / 128, 128>>>(W2, b2, out);
}

// round 8
// speedup vs baseline: 1.5462x; 1.4964x over previous
#include <cuda_runtime.h>
#include <cuda_bf16.h>
#include <cstdint>

#define Nn   40000
#define Ee   640000
#define INF  128
#define HIDF 256
#define CLSF 40
#define MTILES 313
#define MPAD  (MTILES * 128)     // 40064
#define SBLK  157                // ceil(40000/256)

// ---- scratch (device globals; zero-initialized at load) ----
__device__ int    g_deg[Nn];
__device__ int    g_row[Nn + 1];
__device__ int    g_cur[Nn];
__device__ int    g_esrc[Ee];
__device__ int    g_bsum[SBLK];
__device__ int    g_boff[SBLK];
__device__ float  g_norm[MPAD];          // pad rows stay 0
__device__ float  g_norm2[Nn];
__device__ float4 g_buf0[Nn * (INF / 4)];
__device__ float4 g_buf1[MPAD * (INF / 4)];       // pad rows stay 0
__device__ __align__(16) unsigned short g_Bhi[HIDF * INF];  // W1^T bf16 hi, [n][k]
__device__ __align__(16) unsigned short g_Blo[HIDF * INF];  // W1^T bf16 lo
__device__ float4 g_z[Nn * (HIDF / 4)];

// ---------------- degree / CSR build ----------------
__global__ void zero_deg_k() {
    int i = blockIdx.x * blockDim.x + threadIdx.x;
    if (i < Nn) g_deg[i] = 0;
}
__global__ void hist_k(const int* __restrict__ dst) {
    int i = blockIdx.x * blockDim.x + threadIdx.x;
    if (i < Ee) atomicAdd(&g_deg[dst[i]], 1);
}

// ---- parallel hierarchical scan ----
__global__ void bsum_k() {
    __shared__ int ws[8];
    int i = blockIdx.x * 256 + threadIdx.x;
    int v = (i < Nn) ? g_deg[i] : 0;
#pragma unroll
    for (int o = 16; o > 0; o >>= 1) v += __shfl_down_sync(0xffffffffu, v, o);
    int lane = threadIdx.x & 31, w = threadIdx.x >> 5;
    if (lane == 0) ws[w] = v;
    __syncthreads();
    if (w == 0) {
        int s = (lane < 8) ? ws[lane] : 0;
#pragma unroll
        for (int o = 4; o > 0; o >>= 1) s += __shfl_down_sync(0xffffffffu, s, o);
        if (lane == 0) g_bsum[blockIdx.x] = s;
    }
}
__global__ void bscan_k() {       // 1 block, 256 threads; 157 entries
    __shared__ int ws[8];
    int t = threadIdx.x;
    int v = (t < SBLK) ? g_bsum[t] : 0;
    int lane = t & 31, w = t >> 5;
    int inc = v;
#pragma unroll
    for (int o = 1; o < 32; o <<= 1) {
        int n = __shfl_up_sync(0xffffffffu, inc, o);
        if (lane >= o) inc += n;
    }
    if (lane == 31) ws[w] = inc;
    __syncthreads();
    if (w == 0) {
        int s = (lane < 8) ? ws[lane] : 0;
        int si = s;
#pragma unroll
        for (int o = 1; o < 8; o <<= 1) {
            int n = __shfl_up_sync(0xffffffffu, si, o);
            if (lane >= o) si += n;
        }
        if (lane < 8) ws[lane] = si - s;   // exclusive warp base
    }
    __syncthreads();
    if (t < SBLK) g_boff[t] = ws[w] + inc - v;   // exclusive prefix
}
__global__ void fill_k() {
    __shared__ int ws[8];
    int i = blockIdx.x * 256 + threadIdx.x;
    int lane = threadIdx.x & 31, w = threadIdx.x >> 5;
    int d = (i < Nn) ? g_deg[i] : 0;
    int inc = d;
#pragma unroll
    for (int o = 1; o < 32; o <<= 1) {
        int n = __shfl_up_sync(0xffffffffu, inc, o);
        if (lane >= o) inc += n;
    }
    if (lane == 31) ws[w] = inc;
    __syncthreads();
    if (w == 0) {
        int s = (lane < 8) ? ws[lane] : 0;
        int si = s;
#pragma unroll
        for (int o = 1; o < 8; o <<= 1) {
            int n = __shfl_up_sync(0xffffffffu, si, o);
            if (lane >= o) si += n;
        }
        if (lane < 8) ws[lane] = si - s;
    }
    __syncthreads();
    if (i < Nn) {
        int off = g_boff[blockIdx.x] + ws[w] + inc - d;
        g_row[i] = off;
        g_cur[i] = off;
        float nm = rsqrtf(fmaxf((float)d, 1.0f));
        g_norm[i] = nm;
        g_norm2[i] = nm * nm;
    }
}

__global__ void permute_k(const int* __restrict__ src, const int* __restrict__ dst) {
    int i = blockIdx.x * blockDim.x + threadIdx.x;
    if (i < Ee) { int d = dst[i]; int p = atomicAdd(&g_cur[d], 1); g_esrc[p] = src[i]; }
}

// ---------------- propagation (warp-per-node gather) ----------------
__global__ void gather1_k(const float4* __restrict__ xin) {
    int w = (blockIdx.x * blockDim.x + threadIdx.x) >> 5;
    int lane = threadIdx.x & 31;
    if (w >= Nn) return;
    int beg = g_row[w], end = beg + g_deg[w];
    float ax = 0.f, ay = 0.f, az = 0.f, aw = 0.f;
    int e = beg;
    for (; e + 1 < end; e += 2) {
        int s0 = g_esrc[e], s1 = g_esrc[e + 1];
        float w0 = g_norm[s0], w1 = g_norm[s1];
        float4 x0 = xin[s0 * 32 + lane], x1 = xin[s1 * 32 + lane];
        ax += w0 * x0.x + w1 * x1.x; ay += w0 * x0.y + w1 * x1.y;
        az += w0 * x0.z + w1 * x1.z; aw += w0 * x0.w + w1 * x1.w;
    }
    if (e < end) {
        int s0 = g_esrc[e]; float w0 = g_norm[s0];
        float4 x0 = xin[s0 * 32 + lane];
        ax += w0 * x0.x; ay += w0 * x0.y; az += w0 * x0.z; aw += w0 * x0.w;
    }
    g_buf0[w * 32 + lane] = make_float4(ax, ay, az, aw);
}

__global__ void gather2_k() {
    int w = (blockIdx.x * blockDim.x + threadIdx.x) >> 5;
    int lane = threadIdx.x & 31;
    if (w >= Nn) return;
    int beg = g_row[w], end = beg + g_deg[w];
    float ax = 0.f, ay = 0.f, az = 0.f, aw = 0.f;
    int e = beg;
    for (; e + 1 < end; e += 2) {
        int s0 = g_esrc[e], s1 = g_esrc[e + 1];
        float w0 = g_norm2[s0], w1 = g_norm2[s1];
        float4 x0 = g_buf0[s0 * 32 + lane], x1 = g_buf0[s1 * 32 + lane];
        ax += w0 * x0.x + w1 * x1.x; ay += w0 * x0.y + w1 * x1.y;
        az += w0 * x0.z + w1 * x1.z; aw += w0 * x0.w + w1 * x1.w;
    }
    if (e < end) {
        int s0 = g_esrc[e]; float w0 = g_norm2[s0];
        float4 x0 = g_buf0[s0 * 32 + lane];
        ax += w0 * x0.x; ay += w0 * x0.y; az += w0 * x0.z; aw += w0 * x0.w;
    }
    g_buf1[w * 32 + lane] = make_float4(ax, ay, az, aw);
}

// ---- W1 prep: g_B{hi,lo}[n][k] = split-bf16 of W1[k][n] ----
__global__ void prepW1_k(const float* __restrict__ W1) {
    int t = blockIdx.x * blockDim.x + threadIdx.x;   // 8192 threads
    int n = t >> 5, k0 = (t & 31) * 4;
    unsigned short hi[4], lo[4];
#pragma unroll
    for (int i = 0; i < 4; i++) {
        float v = W1[(k0 + i) * HIDF + n];
        __nv_bfloat16 h = __float2bfloat16(v);
        float hf = __bfloat162float(h);
        __nv_bfloat16 l = __float2bfloat16(v - hf);
        hi[i] = __bfloat16_as_ushort(h);
        lo[i] = __bfloat16_as_ushort(l);
    }
    *(uint2*)&g_Bhi[n * INF + k0] =
        make_uint2((uint32_t)hi[1] << 16 | hi[0], (uint32_t)hi[3] << 16 | hi[2]);
    *(uint2*)&g_Blo[n * INF + k0] =
        make_uint2((uint32_t)lo[1] << 16 | lo[0], (uint32_t)lo[3] << 16 | lo[2]);
}

// ---------------- GEMM1 via mma.sync bf16 split (hh+hl+lh) ----------------
#define LDAB 136                 // smem row stride in bf16 elems (272 B)
#define SA_H 0
#define SA_L 34816
#define SB_H 69632
#define SB_L 104448
#define SM_TOT 139264

__device__ __forceinline__ uint32_t smem_u32(const void* p) {
    uint32_t a;
    asm("{ .reg .u64 t; cvta.to.shared.u64 t, %1; cvt.u32.u64 %0, t; }" : "=r"(a) : "l"(p));
    return a;
}
#define LDSM4(R, addr) \
    asm volatile("ldmatrix.sync.aligned.m8n8.x4.shared.b16 {%0,%1,%2,%3}, [%4];" \
        : "=r"((R)[0]), "=r"((R)[1]), "=r"((R)[2]), "=r"((R)[3]) : "r"(addr))
#define MMA16816(C, A, B0, B1) \
    asm volatile("mma.sync.aligned.m16n8k16.row.col.f32.bf16.bf16.f32 " \
        "{%0,%1,%2,%3},{%4,%5,%6,%7},{%8,%9},{%0,%1,%2,%3};" \
        : "+f"((C)[0]), "+f"((C)[1]), "+f"((C)[2]), "+f"((C)[3]) \
        : "r"((A)[0]), "r"((A)[1]), "r"((A)[2]), "r"((A)[3]), "r"(B0), "r"(B1))

__global__ void __launch_bounds__(256, 1) gemm1_mma(const float* __restrict__ b1) {
    extern __shared__ char sm[];
    int tid = threadIdx.x;
    int m0 = blockIdx.x * 128, n0 = blockIdx.y * 128;

    // ---- fill A (hi/lo split, norm folded in) ----
    {
        int mm = tid >> 1, kh = tid & 1;
        float nm = g_norm[m0 + mm];
        const float4* srow = g_buf1 + (size_t)(m0 + mm) * 32 + kh * 16;
        unsigned short* dh = (unsigned short*)(sm + SA_H) + mm * LDAB + kh * 64;
        unsigned short* dl = (unsigned short*)(sm + SA_L) + mm * LDAB + kh * 64;
#pragma unroll
        for (int i = 0; i < 16; i++) {
            float4 v = srow[i];
            float f[4] = {v.x * nm, v.y * nm, v.z * nm, v.w * nm};
            unsigned short hi[4], lo[4];
#pragma unroll
            for (int j = 0; j < 4; j++) {
                __nv_bfloat16 h = __float2bfloat16(f[j]);
                float hf = __bfloat162float(h);
                __nv_bfloat16 l = __float2bfloat16(f[j] - hf);
                hi[j] = __bfloat16_as_ushort(h);
                lo[j] = __bfloat16_as_ushort(l);
            }
            *(uint2*)(dh + i * 4) =
                make_uint2((uint32_t)hi[1] << 16 | hi[0], (uint32_t)hi[3] << 16 | hi[2]);
            *(uint2*)(dl + i * 4) =
                make_uint2((uint32_t)lo[1] << 16 | lo[0], (uint32_t)lo[3] << 16 | lo[2]);
        }
    }
    // ---- copy B tiles (pre-split, transposed) ----
    {
        int nn = tid >> 1, half = tid & 1;
        const uint4* shh = (const uint4*)&g_Bhi[(n0 + nn) * INF + half * 64];
        const uint4* sll = (const uint4*)&g_Blo[(n0 + nn) * INF + half * 64];
        uint4* dh = (uint4*)((unsigned short*)(sm + SB_H) + nn * LDAB + half * 64);
        uint4* dl = (uint4*)((unsigned short*)(sm + SB_L) + nn * LDAB + half * 64);
#pragma unroll
        for (int i = 0; i < 8; i++) { dh[i] = shh[i]; dl[i] = sll[i]; }
    }
    __syncthreads();

    int lane = tid & 31, w = tid >> 5;
    int wm = (w & 3) * 32, wn = (w >> 2) * 64;
    uint32_t sb = smem_u32(sm);

    uint32_t aRow = (uint32_t)(wm + (lane & 15));
    uint32_t aK   = (uint32_t)((lane >> 4) * 8);
    uint32_t aOffH = sb + SA_H + aRow * 272 + aK * 2;
    uint32_t aOffL = sb + SA_L + aRow * 272 + aK * 2;
    uint32_t bRow = (uint32_t)(wn + (lane & 7) + ((lane >> 4) & 1) * 8);
    uint32_t bK   = (uint32_t)(((lane >> 3) & 1) * 8);
    uint32_t bOffH = sb + SB_H + bRow * 272 + bK * 2;
    uint32_t bOffL = sb + SB_L + bRow * 272 + bK * 2;

    float acc[2][8][4];
#pragma unroll
    for (int a = 0; a < 2; a++)
#pragma unroll
        for (int b = 0; b < 8; b++)
#pragma unroll
            for (int c = 0; c < 4; c++) acc[a][b][c] = 0.f;

#pragma unroll
    for (int ks = 0; ks < 8; ks++) {
        uint32_t k2 = (uint32_t)(ks * 32);
        uint32_t Ah[2][4], Al[2][4], Bh[4][4], Bl[4][4];
        LDSM4(Ah[0], aOffH + k2);
        LDSM4(Ah[1], aOffH + k2 + 16 * 272);
        LDSM4(Al[0], aOffL + k2);
        LDSM4(Al[1], aOffL + k2 + 16 * 272);
#pragma unroll
        for (int p = 0; p < 4; p++) {
            LDSM4(Bh[p], bOffH + k2 + p * 16 * 272);
            LDSM4(Bl[p], bOffL + k2 + p * 16 * 272);
        }
#pragma unroll
        for (int mf = 0; mf < 2; mf++) {
#pragma unroll
            for (int nf = 0; nf < 8; nf++) {
                int p = nf >> 1, s = (nf & 1) * 2;
                MMA16816(acc[mf][nf], Ah[mf], Bh[p][s], Bh[p][s + 1]);   // hh
                MMA16816(acc[mf][nf], Ah[mf], Bl[p][s], Bl[p][s + 1]);   // hl
                MMA16816(acc[mf][nf], Al[mf], Bh[p][s], Bh[p][s + 1]);   // lh
            }
        }
    }

    int g = lane >> 2, t = lane & 3;
    float* zf = (float*)g_z;
#pragma unroll
    for (int mf = 0; mf < 2; mf++) {
        int r0 = m0 + wm + mf * 16 + g;
        int r1 = r0 + 8;
#pragma unroll
        for (int nf = 0; nf < 8; nf++) {
            int col = n0 + wn + nf * 8 + t * 2;
            float2 bb = *(const float2*)&b1[col];
            if (r0 < Nn) {
                float2 o;
                o.x = fmaxf(acc[mf][nf][0] + bb.x, 0.f);
                o.y = fmaxf(acc[mf][nf][1] + bb.y, 0.f);
                *(float2*)&zf[(size_t)r0 * HIDF + col] = o;
            }
            if (r1 < Nn) {
                float2 o;
                o.x = fmaxf(acc[mf][nf][2] + bb.x, 0.f);
                o.y = fmaxf(acc[mf][nf][3] + bb.y, 0.f);
                *(float2*)&zf[(size_t)r1 * HIDF + col] = o;
            }
        }
    }
}

// ---------------- GEMM2: out = z @ W2 + b2 ----------------
__global__ void gemm2_k(const float* __restrict__ W2, const float* __restrict__ b2,
                        float* __restrict__ out) {
    __shared__ float W2s[32][CLSF];
    int tid = threadIdx.x;
    int row = blockIdx.x * 128 + tid;
    float acc[CLSF];
#pragma unroll
    for (int c = 0; c < CLSF; c++) acc[c] = 0.f;
    const float* zf = (const float*)g_z;
    for (int kc = 0; kc < HIDF; kc += 32) {
        for (int i = tid; i < 32 * CLSF; i += 128) {
            int r = i / CLSF, c = i % CLSF;
            W2s[r][c] = W2[(kc + r) * CLSF + c];
        }
        __syncthreads();
        if (row < Nn) {
            const float4* zr = (const float4*)&zf[(size_t)row * HIDF + kc];
#pragma unroll
            for (int j = 0; j < 8; j++) {
                float4 z4 = zr[j];
                float zz[4] = {z4.x, z4.y, z4.z, z4.w};
#pragma unroll
                for (int q = 0; q < 4; q++) {
                    float zv = zz[q];
                    int k = j * 4 + q;
#pragma unroll
                    for (int c4 = 0; c4 < CLSF / 4; c4++) {
                        float4 wv = *(const float4*)&W2s[k][c4 * 4];
                        acc[c4 * 4 + 0] += zv * wv.x;
                        acc[c4 * 4 + 1] += zv * wv.y;
                        acc[c4 * 4 + 2] += zv * wv.z;
                        acc[c4 * 4 + 3] += zv * wv.w;
                    }
                }
            }
        }
        __syncthreads();
    }
    if (row < Nn) {
#pragma unroll
        for (int c = 0; c < CLSF; c++) out[row * CLSF + c] = acc[c] + b2[c];
    }
}

extern "C" void kernel_launch(void* const* d_in, const int* in_sizes, int n_in,
                              void* d_out, int out_size) {
    const float* features = (const float*)d_in[0];
    const int*   src      = (const int*)d_in[1];
    const int*   dst      = (const int*)d_in[2];
    const float* W1       = (const float*)d_in[3];
    const float* b1       = (const float*)d_in[4];
    const float* W2       = (const float*)d_in[5];
    const float* b2       = (const float*)d_in[6];
    float*       out      = (float*)d_out;

    cudaFuncSetAttribute(gemm1_mma, cudaFuncAttributeMaxDynamicSharedMemorySize, SM_TOT);

    zero_deg_k<<<(Nn + 255) / 256, 256>>>();
    hist_k<<<(Ee + 255) / 256, 256>>>(dst);
    prepW1_k<<<32, 256>>>(W1);
    bsum_k<<<SBLK, 256>>>();
    bscan_k<<<1, 256>>>();
    fill_k<<<SBLK, 256>>>();
    permute_k<<<(Ee + 255) / 256, 256>>>(src, dst);

    gather1_k<<<Nn / 8, 256>>>((const float4*)features);
    gather2_k<<<Nn / 8, 256>>>();

    gemm1_mma<<<dim3(MTILES, 2), 256, SM_TOT>>>(b1);
    gemm2_k<<<(Nn + 127) / 128, 128>>>(W2, b2, out);
}

// round 10
// speedup vs baseline: 2.0486x; 1.3249x over previous
#include <cuda_runtime.h>
#include <cuda_bf16.h>
#include <cstdint>

#define Nn   40000
#define Ee   640000
#define INF  128
#define HIDF 256
#define CLSF 40
#define MTILES 313
#define MPAD  (MTILES * 128)     // 40064
#define SBLK  157                // ceil(40000/256)
#define W2N   48                 // padded n for W2^T
#define W2LD  264                // padded k stride (528B rows)

// ---- scratch (device globals; zero-initialized at load) ----
__device__ int    g_deg[Nn];
__device__ int    g_row[Nn + 1];
__device__ int    g_cur[Nn];
__device__ int    g_esrc[Ee];
__device__ int    g_bsum[SBLK];
__device__ int    g_boff[SBLK];
__device__ float  g_norm[MPAD];          // pad rows stay 0
__device__ float  g_norm2[Nn];
__device__ float4 g_buf0[Nn * (INF / 4)];
__device__ float4 g_buf1[MPAD * (INF / 4)];       // pad rows stay 0
__device__ __align__(16) unsigned short g_Bhi[HIDF * INF];  // W1^T bf16 hi, [n][k]
__device__ __align__(16) unsigned short g_Blo[HIDF * INF];  // W1^T bf16 lo
__device__ __align__(16) unsigned short g_W2h[W2N * W2LD];  // W2^T bf16 hi
__device__ __align__(16) unsigned short g_W2l[W2N * W2LD];  // W2^T bf16 lo
__device__ float  g_part[4][Nn * CLSF];                     // gemm2 partials

// ---------------- degree / CSR build ----------------
__global__ void zero_deg_k() {
    int i = blockIdx.x * blockDim.x + threadIdx.x;
    if (i < Nn) g_deg[i] = 0;
}
__global__ void hist_k(const int* __restrict__ dst) {
    int i = blockIdx.x * blockDim.x + threadIdx.x;
    if (i < Ee) atomicAdd(&g_deg[dst[i]], 1);
}

// ---- parallel hierarchical scan ----
__global__ void bsum_k() {
    __shared__ int ws[8];
    int i = blockIdx.x * 256 + threadIdx.x;
    int v = (i < Nn) ? g_deg[i] : 0;
#pragma unroll
    for (int o = 16; o > 0; o >>= 1) v += __shfl_down_sync(0xffffffffu, v, o);
    int lane = threadIdx.x & 31, w = threadIdx.x >> 5;
    if (lane == 0) ws[w] = v;
    __syncthreads();
    if (w == 0) {
        int s = (lane < 8) ? ws[lane] : 0;
#pragma unroll
        for (int o = 4; o > 0; o >>= 1) s += __shfl_down_sync(0xffffffffu, s, o);
        if (lane == 0) g_bsum[blockIdx.x] = s;
    }
}
__global__ void bscan_k() {
    __shared__ int ws[8];
    int t = threadIdx.x;
    int v = (t < SBLK) ? g_bsum[t] : 0;
    int lane = t & 31, w = t >> 5;
    int inc = v;
#pragma unroll
    for (int o = 1; o < 32; o <<= 1) {
        int n = __shfl_up_sync(0xffffffffu, inc, o);
        if (lane >= o) inc += n;
    }
    if (lane == 31) ws[w] = inc;
    __syncthreads();
    if (w == 0) {
        int s = (lane < 8) ? ws[lane] : 0;
        int si = s;
#pragma unroll
        for (int o = 1; o < 8; o <<= 1) {
            int n = __shfl_up_sync(0xffffffffu, si, o);
            if (lane >= o) si += n;
        }
        if (lane < 8) ws[lane] = si - s;
    }
    __syncthreads();
    if (t < SBLK) g_boff[t] = ws[w] + inc - v;
}
__global__ void fill_k() {
    __shared__ int ws[8];
    int i = blockIdx.x * 256 + threadIdx.x;
    int lane = threadIdx.x & 31, w = threadIdx.x >> 5;
    int d = (i < Nn) ? g_deg[i] : 0;
    int inc = d;
#pragma unroll
    for (int o = 1; o < 32; o <<= 1) {
        int n = __shfl_up_sync(0xffffffffu, inc, o);
        if (lane >= o) inc += n;
    }
    if (lane == 31) ws[w] = inc;
    __syncthreads();
    if (w == 0) {
        int s = (lane < 8) ? ws[lane] : 0;
        int si = s;
#pragma unroll
        for (int o = 1; o < 8; o <<= 1) {
            int n = __shfl_up_sync(0xffffffffu, si, o);
            if (lane >= o) si += n;
        }
        if (lane < 8) ws[lane] = si - s;
    }
    __syncthreads();
    if (i < Nn) {
        int off = g_boff[blockIdx.x] + ws[w] + inc - d;
        g_row[i] = off;
        g_cur[i] = off;
        float nm = rsqrtf(fmaxf((float)d, 1.0f));
        g_norm[i] = nm;
        g_norm2[i] = nm * nm;
    }
}

__global__ void permute_k(const int* __restrict__ src, const int* __restrict__ dst) {
    int i = blockIdx.x * blockDim.x + threadIdx.x;
    if (i < Ee) { int d = dst[i]; int p = atomicAdd(&g_cur[d], 1); g_esrc[p] = src[i]; }
}

// ---------------- propagation (warp-per-node gather) ----------------
__global__ void gather1_k(const float4* __restrict__ xin) {
    int w = (blockIdx.x * blockDim.x + threadIdx.x) >> 5;
    int lane = threadIdx.x & 31;
    if (w >= Nn) return;
    int beg = g_row[w], end = beg + g_deg[w];
    float ax = 0.f, ay = 0.f, az = 0.f, aw = 0.f;
    int e = beg;
    for (; e + 1 < end; e += 2) {
        int s0 = g_esrc[e], s1 = g_esrc[e + 1];
        float w0 = g_norm[s0], w1 = g_norm[s1];
        float4 x0 = xin[s0 * 32 + lane], x1 = xin[s1 * 32 + lane];
        ax += w0 * x0.x + w1 * x1.x; ay += w0 * x0.y + w1 * x1.y;
        az += w0 * x0.z + w1 * x1.z; aw += w0 * x0.w + w1 * x1.w;
    }
    if (e < end) {
        int s0 = g_esrc[e]; float w0 = g_norm[s0];
        float4 x0 = xin[s0 * 32 + lane];
        ax += w0 * x0.x; ay += w0 * x0.y; az += w0 * x0.z; aw += w0 * x0.w;
    }
    g_buf0[w * 32 + lane] = make_float4(ax, ay, az, aw);
}

__global__ void gather2_k() {
    int w = (blockIdx.x * blockDim.x + threadIdx.x) >> 5;
    int lane = threadIdx.x & 31;
    if (w >= Nn) return;
    int beg = g_row[w], end = beg + g_deg[w];
    float ax = 0.f, ay = 0.f, az = 0.f, aw = 0.f;
    int e = beg;
    for (; e + 1 < end; e += 2) {
        int s0 = g_esrc[e], s1 = g_esrc[e + 1];
        float w0 = g_norm2[s0], w1 = g_norm2[s1];
        float4 x0 = g_buf0[s0 * 32 + lane], x1 = g_buf0[s1 * 32 + lane];
        ax += w0 * x0.x + w1 * x1.x; ay += w0 * x0.y + w1 * x1.y;
        az += w0 * x0.z + w1 * x1.z; aw += w0 * x0.w + w1 * x1.w;
    }
    if (e < end) {
        int s0 = g_esrc[e]; float w0 = g_norm2[s0];
        float4 x0 = g_buf0[s0 * 32 + lane];
        ax += w0 * x0.x; ay += w0 * x0.y; az += w0 * x0.z; aw += w0 * x0.w;
    }
    g_buf1[w * 32 + lane] = make_float4(ax, ay, az, aw);
}

// ---- W1 prep ----
__global__ void prepW1_k(const float* __restrict__ W1) {
    int t = blockIdx.x * blockDim.x + threadIdx.x;   // 8192 threads
    int n = t >> 5, k0 = (t & 31) * 4;
    unsigned short hi[4], lo[4];
#pragma unroll
    for (int i = 0; i < 4; i++) {
        float v = W1[(k0 + i) * HIDF + n];
        __nv_bfloat16 h = __float2bfloat16(v);
        float hf = __bfloat162float(h);
        __nv_bfloat16 l = __float2bfloat16(v - hf);
        hi[i] = __bfloat16_as_ushort(h);
        lo[i] = __bfloat16_as_ushort(l);
    }
    *(uint2*)&g_Bhi[n * INF + k0] =
        make_uint2((uint32_t)hi[1] << 16 | hi[0], (uint32_t)hi[3] << 16 | hi[2]);
    *(uint2*)&g_Blo[n * INF + k0] =
        make_uint2((uint32_t)lo[1] << 16 | lo[0], (uint32_t)lo[3] << 16 | lo[2]);
}

// ---- W2 prep: split hi/lo, transposed [n][k], padded ----
__global__ void prepW2_k(const float* __restrict__ W2) {
    int t = blockIdx.x * blockDim.x + threadIdx.x;   // 2560 threads
    if (t >= CLSF * 64) return;
    int n = t >> 6, k0 = (t & 63) * 4;
    unsigned short hi[4], lo[4];
#pragma unroll
    for (int i = 0; i < 4; i++) {
        float v = W2[(k0 + i) * CLSF + n];
        __nv_bfloat16 h = __float2bfloat16(v);
        float hf = __bfloat162float(h);
        hi[i] = __bfloat16_as_ushort(h);
        lo[i] = __bfloat16_as_ushort(__float2bfloat16(v - hf));
    }
    *(uint2*)&g_W2h[n * W2LD + k0] =
        make_uint2((uint32_t)hi[1] << 16 | hi[0], (uint32_t)hi[3] << 16 | hi[2]);
    *(uint2*)&g_W2l[n * W2LD + k0] =
        make_uint2((uint32_t)lo[1] << 16 | lo[0], (uint32_t)lo[3] << 16 | lo[2]);
}

// ---------------- fused GEMM1+GEMM2 via mma.sync ----------------
#define LDAB 136
#define SA_H 0
#define SA_L 34816
#define SB_H 69632
#define SB_L 104448
#define SW2H 139264              // 48*264*2 = 25344 B
#define SW2L 164608
#define SM_TOT (164608 + 25344)  // 189952

__device__ __forceinline__ uint32_t smem_u32(const void* p) {
    uint32_t a;
    asm("{ .reg .u64 t; cvta.to.shared.u64 t, %1; cvt.u32.u64 %0, t; }" : "=r"(a) : "l"(p));
    return a;
}
#define LDSM4(R, addr) \
    asm volatile("ldmatrix.sync.aligned.m8n8.x4.shared.b16 {%0,%1,%2,%3}, [%4];" \
        : "=r"((R)[0]), "=r"((R)[1]), "=r"((R)[2]), "=r"((R)[3]) : "r"(addr))
#define MMA16816(C, A, B0, B1) \
    asm volatile("mma.sync.aligned.m16n8k16.row.col.f32.bf16.bf16.f32 " \
        "{%0,%1,%2,%3},{%4,%5,%6,%7},{%8,%9},{%0,%1,%2,%3};" \
        : "+f"((C)[0]), "+f"((C)[1]), "+f"((C)[2]), "+f"((C)[3]) \
        : "r"((A)[0]), "r"((A)[1]), "r"((A)[2]), "r"((A)[3]), "r"(B0), "r"(B1))

__device__ __forceinline__ void split2(float a, float b, uint32_t& hi, uint32_t& lo) {
    __nv_bfloat16 ha = __float2bfloat16(a), hb = __float2bfloat16(b);
    float la = a - __bfloat162float(ha), lb = b - __bfloat162float(hb);
    hi = ((uint32_t)__bfloat16_as_ushort(hb) << 16) | __bfloat16_as_ushort(ha);
    lo = ((uint32_t)__bfloat16_as_ushort(__float2bfloat16(lb)) << 16) |
         __bfloat16_as_ushort(__float2bfloat16(la));
}

__global__ void __launch_bounds__(256, 1) gemm1_fused(const float* __restrict__ b1) {
    extern __shared__ char sm[];
    int tid = threadIdx.x;
    int m0 = blockIdx.x * 128, n0 = blockIdx.y * 128;

    // ---- fill A (hi/lo split, norm folded in) ----
    {
        int mm = tid >> 1, kh = tid & 1;
        float nm = g_norm[m0 + mm];
        const float4* srow = g_buf1 + (size_t)(m0 + mm) * 32 + kh * 16;
        unsigned short* dh = (unsigned short*)(sm + SA_H) + mm * LDAB + kh * 64;
        unsigned short* dl = (unsigned short*)(sm + SA_L) + mm * LDAB + kh * 64;
#pragma unroll
        for (int i = 0; i < 16; i++) {
            float4 v = srow[i];
            float f[4] = {v.x * nm, v.y * nm, v.z * nm, v.w * nm};
            unsigned short hi[4], lo[4];
#pragma unroll
            for (int j = 0; j < 4; j++) {
                __nv_bfloat16 h = __float2bfloat16(f[j]);
                float hf = __bfloat162float(h);
                __nv_bfloat16 l = __float2bfloat16(f[j] - hf);
                hi[j] = __bfloat16_as_ushort(h);
                lo[j] = __bfloat16_as_ushort(l);
            }
            *(uint2*)(dh + i * 4) =
                make_uint2((uint32_t)hi[1] << 16 | hi[0], (uint32_t)hi[3] << 16 | hi[2]);
            *(uint2*)(dl + i * 4) =
                make_uint2((uint32_t)lo[1] << 16 | lo[0], (uint32_t)lo[3] << 16 | lo[2]);
        }
    }
    // ---- copy B (W1^T) tiles ----
    {
        int nn = tid >> 1, half = tid & 1;
        const uint4* shh = (const uint4*)&g_Bhi[(n0 + nn) * INF + half * 64];
        const uint4* sll = (const uint4*)&g_Blo[(n0 + nn) * INF + half * 64];
        uint4* dh = (uint4*)((unsigned short*)(sm + SB_H) + nn * LDAB + half * 64);
        uint4* dl = (uint4*)((unsigned short*)(sm + SB_L) + nn * LDAB + half * 64);
#pragma unroll
        for (int i = 0; i < 8; i++) { dh[i] = shh[i]; dl[i] = sll[i]; }
    }
    // ---- copy W2^T hi/lo (48x264 bf16 each) ----
    {
        const uint4* sh = (const uint4*)g_W2h;
        const uint4* sl = (const uint4*)g_W2l;
        uint4* dh = (uint4*)(sm + SW2H);
        uint4* dl = (uint4*)(sm + SW2L);
#pragma unroll
        for (int i = 0; i < 7; i++) {
            int idx = tid + i * 256;
            if (idx < (W2N * W2LD * 2) / 16) { dh[idx] = sh[idx]; dl[idx] = sl[idx]; }
        }
    }
    __syncthreads();

    int lane = tid & 31, w = tid >> 5;
    int wm = (w & 3) * 32, wn = (w >> 2) * 64;
    uint32_t sb = smem_u32(sm);

    uint32_t aRow = (uint32_t)(wm + (lane & 15));
    uint32_t aK   = (uint32_t)((lane >> 4) * 8);
    uint32_t aOffH = sb + SA_H + aRow * 272 + aK * 2;
    uint32_t aOffL = sb + SA_L + aRow * 272 + aK * 2;
    uint32_t bRow = (uint32_t)(wn + (lane & 7) + ((lane >> 4) & 1) * 8);
    uint32_t bK   = (uint32_t)(((lane >> 3) & 1) * 8);
    uint32_t bOffH = sb + SB_H + bRow * 272 + bK * 2;
    uint32_t bOffL = sb + SB_L + bRow * 272 + bK * 2;

    float acc[2][8][4];
#pragma unroll
    for (int a = 0; a < 2; a++)
#pragma unroll
        for (int b = 0; b < 8; b++)
#pragma unroll
            for (int c = 0; c < 4; c++) acc[a][b][c] = 0.f;

#pragma unroll
    for (int ks = 0; ks < 8; ks++) {
        uint32_t k2 = (uint32_t)(ks * 32);
        uint32_t Ah[2][4], Al[2][4], Bh[4][4], Bl[4][4];
        LDSM4(Ah[0], aOffH + k2);
        LDSM4(Ah[1], aOffH + k2 + 16 * 272);
        LDSM4(Al[0], aOffL + k2);
        LDSM4(Al[1], aOffL + k2 + 16 * 272);
#pragma unroll
        for (int p = 0; p < 4; p++) {
            LDSM4(Bh[p], bOffH + k2 + p * 16 * 272);
            LDSM4(Bl[p], bOffL + k2 + p * 16 * 272);
        }
#pragma unroll
        for (int mf = 0; mf < 2; mf++) {
#pragma unroll
            for (int nf = 0; nf < 8; nf++) {
                int p = nf >> 1, s = (nf & 1) * 2;
                MMA16816(acc[mf][nf], Ah[mf], Bh[p][s], Bh[p][s + 1]);   // hh
                MMA16816(acc[mf][nf], Ah[mf], Bl[p][s], Bl[p][s + 1]);   // hl
                MMA16816(acc[mf][nf], Al[mf], Bh[p][s], Bh[p][s + 1]);   // lh
            }
        }
    }

    // ---- bias + relu in registers ----
    int t = lane & 3;
#pragma unroll
    for (int nf = 0; nf < 8; nf++) {
        int col = n0 + wn + nf * 8 + t * 2;
        float2 bb = *(const float2*)&b1[col];
#pragma unroll
        for (int mf = 0; mf < 2; mf++) {
            acc[mf][nf][0] = fmaxf(acc[mf][nf][0] + bb.x, 0.f);
            acc[mf][nf][1] = fmaxf(acc[mf][nf][1] + bb.y, 0.f);
            acc[mf][nf][2] = fmaxf(acc[mf][nf][2] + bb.x, 0.f);
            acc[mf][nf][3] = fmaxf(acc[mf][nf][3] + bb.y, 0.f);
        }
    }

    // ---- gemm2: 3-pass split (zh@Wh + zh@Wl + zl@Wh), k-slice = warp's 64 cols ----
    float oacc[2][5][4];
#pragma unroll
    for (int a = 0; a < 2; a++)
#pragma unroll
        for (int b = 0; b < 5; b++)
#pragma unroll
            for (int c = 0; c < 4; c++) oacc[a][b][c] = 0.f;

    uint32_t w2row = (uint32_t)((lane & 7) + ((lane >> 4) & 1) * 8);
    uint32_t w2kh  = (uint32_t)(((lane >> 3) & 1) * 16);
    uint32_t w2baseH = sb + SW2H + w2row * (W2LD * 2) + w2kh;
    uint32_t w2baseL = sb + SW2L + w2row * (W2LD * 2) + w2kh;

#pragma unroll
    for (int c = 0; c < 4; c++) {
        uint32_t kb = (uint32_t)((n0 + wn + 16 * c) * 2);
        uint32_t Bqh[3][4], Bql[3][4];
#pragma unroll
        for (int p = 0; p < 3; p++) {
            LDSM4(Bqh[p], w2baseH + p * 16 * (W2LD * 2) + kb);
            LDSM4(Bql[p], w2baseL + p * 16 * (W2LD * 2) + kb);
        }
#pragma unroll
        for (int mf = 0; mf < 2; mf++) {
            uint32_t zh[4], zl[4];
            split2(acc[mf][2 * c][0],     acc[mf][2 * c][1],     zh[0], zl[0]);
            split2(acc[mf][2 * c][2],     acc[mf][2 * c][3],     zh[1], zl[1]);
            split2(acc[mf][2 * c + 1][0], acc[mf][2 * c + 1][1], zh[2], zl[2]);
            split2(acc[mf][2 * c + 1][2], acc[mf][2 * c + 1][3], zh[3], zl[3]);
#pragma unroll
            for (int o = 0; o < 5; o++) {
                int p = o >> 1, s = (o & 1) * 2;
                MMA16816(oacc[mf][o], zh, Bqh[p][s], Bqh[p][s + 1]);   // zh @ Wh
                MMA16816(oacc[mf][o], zh, Bql[p][s], Bql[p][s + 1]);   // zh @ Wl
                MMA16816(oacc[mf][o], zl, Bqh[p][s], Bqh[p][s + 1]);   // zl @ Wh
            }
        }
    }

    // ---- write partials ----
    int bufid = blockIdx.y * 2 + (w >> 2);
    int g = lane >> 2;
    float* part = g_part[bufid];
#pragma unroll
    for (int mf = 0; mf < 2; mf++) {
        int r0 = m0 + wm + mf * 16 + g;
        int r1 = r0 + 8;
#pragma unroll
        for (int o = 0; o < 5; o++) {
            int col = o * 8 + t * 2;
            if (r0 < Nn) *(float2*)&part[(size_t)r0 * CLSF + col] =
                make_float2(oacc[mf][o][0], oacc[mf][o][1]);
            if (r1 < Nn) *(float2*)&part[(size_t)r1 * CLSF + col] =
                make_float2(oacc[mf][o][2], oacc[mf][o][3]);
        }
    }
}

// ---------------- combine: out = sum(parts) + b2 ----------------
__global__ void combine_k(const float* __restrict__ b2, float* __restrict__ out) {
    int i = blockIdx.x * 256 + threadIdx.x;      // float2 index
    if (i >= Nn * CLSF / 2) return;
    const float2* p0 = (const float2*)g_part[0];
    const float2* p1 = (const float2*)g_part[1];
    const float2* p2 = (const float2*)g_part[2];
    const float2* p3 = (const float2*)g_part[3];
    float2 a = p0[i], b = p1[i], c = p2[i], d = p3[i];
    int col2 = i % (CLSF / 2);
    float2 bb = *(const float2*)&b2[col2 * 2];
    float2 o;
    o.x = a.x + b.x + c.x + d.x + bb.x;
    o.y = a.y + b.y + c.y + d.y + bb.y;
    ((float2*)out)[i] = o;
}

extern "C" void kernel_launch(void* const* d_in, const int* in_sizes, int n_in,
                              void* d_out, int out_size) {
    const float* features = (const float*)d_in[0];
    const int*   src      = (const int*)d_in[1];
    const int*   dst      = (const int*)d_in[2];
    const float* W1       = (const float*)d_in[3];
    const float* b1       = (const float*)d_in[4];
    const float* W2       = (const float*)d_in[5];
    const float* b2       = (const float*)d_in[6];
    float*       out      = (float*)d_out;

    cudaFuncSetAttribute(gemm1_fused, cudaFuncAttributeMaxDynamicSharedMemorySize, SM_TOT);

    zero_deg_k<<<(Nn + 255) / 256, 256>>>();
    hist_k<<<(Ee + 255) / 256, 256>>>(dst);
    prepW1_k<<<32, 256>>>(W1);
    prepW2_k<<<10, 256>>>(W2);
    bsum_k<<<SBLK, 256>>>();
    bscan_k<<<1, 256>>>();
    fill_k<<<SBLK, 256>>>();
    permute_k<<<(Ee + 255) / 256, 256>>>(src, dst);

    gather1_k<<<Nn / 8, 256>>>((const float4*)features);
    gather2_k<<<Nn / 8, 256>>>();

    gemm1_fused<<<dim3(MTILES, 2), 256, SM_TOT>>>(b1);
    combine_k<<<(Nn * CLSF / 2 + 255) / 256, 256>>>(b2, out);
}

// round 11
// speedup vs baseline: 2.4944x; 1.2176x over previous
#include <cuda_runtime.h>
#include <cuda_fp16.h>
#include <cstdint>

#define Nn   40000
#define Ee   640000
#define INF  128
#define HIDF 256
#define CLSF 40
#define MTILES 313
#define MPAD  (MTILES * 128)     // 40064
#define SBLK  157                // ceil(40000/256)
#define W2N   48                 // padded n for W2^T
#define W2LD  264                // padded k stride (528B rows)

// ---- scratch (device globals; zero-initialized at load) ----
__device__ int    g_deg[Nn];
__device__ int    g_row[Nn + 1];
__device__ int    g_cur[Nn];
__device__ int    g_esrc[Ee];
__device__ int    g_bsum[SBLK];
__device__ int    g_boff[SBLK];
__device__ float  g_norm[Nn];
__device__ float  g_norm2[Nn];
__device__ float4 g_buf0[Nn * (INF / 4)];
__device__ __align__(16) __half g_Ah[MPAD * INF];           // norm.*A^2x as fp16, pad rows 0
__device__ __align__(16) unsigned short g_Bh[HIDF * INF];   // W1^T fp16 hi, [n][k]
__device__ __align__(16) unsigned short g_Bl[HIDF * INF];   // W1^T fp16 lo
__device__ __align__(16) unsigned short g_W2h[W2N * W2LD];  // W2^T fp16 hi
__device__ __align__(16) unsigned short g_W2l[W2N * W2LD];  // W2^T fp16 lo
__device__ float  g_part[4][Nn * CLSF];                     // gemm2 partials

// ---------------- degree / CSR build ----------------
__global__ void zero_deg_k() {
    int i = blockIdx.x * blockDim.x + threadIdx.x;
    if (i < Nn) g_deg[i] = 0;
}
__global__ void hist_k(const int* __restrict__ dst) {
    int i = blockIdx.x * blockDim.x + threadIdx.x;
    if (i < Ee) atomicAdd(&g_deg[dst[i]], 1);
}

// ---- parallel hierarchical scan ----
__global__ void bsum_k() {
    __shared__ int ws[8];
    int i = blockIdx.x * 256 + threadIdx.x;
    int v = (i < Nn) ? g_deg[i] : 0;
#pragma unroll
    for (int o = 16; o > 0; o >>= 1) v += __shfl_down_sync(0xffffffffu, v, o);
    int lane = threadIdx.x & 31, w = threadIdx.x >> 5;
    if (lane == 0) ws[w] = v;
    __syncthreads();
    if (w == 0) {
        int s = (lane < 8) ? ws[lane] : 0;
#pragma unroll
        for (int o = 4; o > 0; o >>= 1) s += __shfl_down_sync(0xffffffffu, s, o);
        if (lane == 0) g_bsum[blockIdx.x] = s;
    }
}
__global__ void bscan_k() {
    __shared__ int ws[8];
    int t = threadIdx.x;
    int v = (t < SBLK) ? g_bsum[t] : 0;
    int lane = t & 31, w = t >> 5;
    int inc = v;
#pragma unroll
    for (int o = 1; o < 32; o <<= 1) {
        int n = __shfl_up_sync(0xffffffffu, inc, o);
        if (lane >= o) inc += n;
    }
    if (lane == 31) ws[w] = inc;
    __syncthreads();
    if (w == 0) {
        int s = (lane < 8) ? ws[lane] : 0;
        int si = s;
#pragma unroll
        for (int o = 1; o < 8; o <<= 1) {
            int n = __shfl_up_sync(0xffffffffu, si, o);
            if (lane >= o) si += n;
        }
        if (lane < 8) ws[lane] = si - s;
    }
    __syncthreads();
    if (t < SBLK) g_boff[t] = ws[w] + inc - v;
}
__global__ void fill_k() {
    __shared__ int ws[8];
    int i = blockIdx.x * 256 + threadIdx.x;
    int lane = threadIdx.x & 31, w = threadIdx.x >> 5;
    int d = (i < Nn) ? g_deg[i] : 0;
    int inc = d;
#pragma unroll
    for (int o = 1; o < 32; o <<= 1) {
        int n = __shfl_up_sync(0xffffffffu, inc, o);
        if (lane >= o) inc += n;
    }
    if (lane == 31) ws[w] = inc;
    __syncthreads();
    if (w == 0) {
        int s = (lane < 8) ? ws[lane] : 0;
        int si = s;
#pragma unroll
        for (int o = 1; o < 8; o <<= 1) {
            int n = __shfl_up_sync(0xffffffffu, si, o);
            if (lane >= o) si += n;
        }
        if (lane < 8) ws[lane] = si - s;
    }
    __syncthreads();
    if (i < Nn) {
        int off = g_boff[blockIdx.x] + ws[w] + inc - d;
        g_row[i] = off;
        g_cur[i] = off;
        float nm = rsqrtf(fmaxf((float)d, 1.0f));
        g_norm[i] = nm;
        g_norm2[i] = nm * nm;
    }
}

__global__ void permute_k(const int* __restrict__ src, const int* __restrict__ dst) {
    int i = blockIdx.x * blockDim.x + threadIdx.x;
    if (i < Ee) { int d = dst[i]; int p = atomicAdd(&g_cur[d], 1); g_esrc[p] = src[i]; }
}

// ---------------- propagation (warp-per-node gather, unroll 4) ----------------
__global__ void gather1_k(const float4* __restrict__ xin) {
    int w = (blockIdx.x * blockDim.x + threadIdx.x) >> 5;
    int lane = threadIdx.x & 31;
    if (w >= Nn) return;
    int beg = g_row[w], end = beg + g_deg[w];
    float ax = 0.f, ay = 0.f, az = 0.f, aw = 0.f;
    int e = beg;
    for (; e + 3 < end; e += 4) {
        int s0 = g_esrc[e], s1 = g_esrc[e + 1], s2 = g_esrc[e + 2], s3 = g_esrc[e + 3];
        float w0 = g_norm[s0], w1 = g_norm[s1], w2 = g_norm[s2], w3 = g_norm[s3];
        float4 x0 = xin[s0 * 32 + lane], x1 = xin[s1 * 32 + lane];
        float4 x2 = xin[s2 * 32 + lane], x3 = xin[s3 * 32 + lane];
        ax += w0 * x0.x + w1 * x1.x + w2 * x2.x + w3 * x3.x;
        ay += w0 * x0.y + w1 * x1.y + w2 * x2.y + w3 * x3.y;
        az += w0 * x0.z + w1 * x1.z + w2 * x2.z + w3 * x3.z;
        aw += w0 * x0.w + w1 * x1.w + w2 * x2.w + w3 * x3.w;
    }
    for (; e < end; e++) {
        int s0 = g_esrc[e]; float w0 = g_norm[s0];
        float4 x0 = xin[s0 * 32 + lane];
        ax += w0 * x0.x; ay += w0 * x0.y; az += w0 * x0.z; aw += w0 * x0.w;
    }
    g_buf0[w * 32 + lane] = make_float4(ax, ay, az, aw);
}

// hop 2 + fold norm[w] + emit fp16 row-major [m][k]
__global__ void gather2_k() {
    int w = (blockIdx.x * blockDim.x + threadIdx.x) >> 5;
    int lane = threadIdx.x & 31;
    if (w >= Nn) return;
    int beg = g_row[w], end = beg + g_deg[w];
    float ax = 0.f, ay = 0.f, az = 0.f, aw = 0.f;
    int e = beg;
    for (; e + 3 < end; e += 4) {
        int s0 = g_esrc[e], s1 = g_esrc[e + 1], s2 = g_esrc[e + 2], s3 = g_esrc[e + 3];
        float w0 = g_norm2[s0], w1 = g_norm2[s1], w2 = g_norm2[s2], w3 = g_norm2[s3];
        float4 x0 = g_buf0[s0 * 32 + lane], x1 = g_buf0[s1 * 32 + lane];
        float4 x2 = g_buf0[s2 * 32 + lane], x3 = g_buf0[s3 * 32 + lane];
        ax += w0 * x0.x + w1 * x1.x + w2 * x2.x + w3 * x3.x;
        ay += w0 * x0.y + w1 * x1.y + w2 * x2.y + w3 * x3.y;
        az += w0 * x0.z + w1 * x1.z + w2 * x2.z + w3 * x3.z;
        aw += w0 * x0.w + w1 * x1.w + w2 * x2.w + w3 * x3.w;
    }
    for (; e < end; e++) {
        int s0 = g_esrc[e]; float w0 = g_norm2[s0];
        float4 x0 = g_buf0[s0 * 32 + lane];
        ax += w0 * x0.x; ay += w0 * x0.y; az += w0 * x0.z; aw += w0 * x0.w;
    }
    float nw = g_norm[w];
    __half2 p0 = __floats2half2_rn(ax * nw, ay * nw);
    __half2 p1 = __floats2half2_rn(az * nw, aw * nw);
    uint2 pk;
    pk.x = *(uint32_t*)&p0;
    pk.y = *(uint32_t*)&p1;
    *(uint2*)&g_Ah[(size_t)w * INF + lane * 4] = pk;
}

// ---- weight prep: W1^T and W2^T, fp16 hi/lo split ----
__global__ void prepW_k(const float* __restrict__ W1, const float* __restrict__ W2) {
    int t = blockIdx.x * blockDim.x + threadIdx.x;
    if (t < 8192) {                         // W1: n = t>>5 (256), k0 = (t&31)*4
        int n = t >> 5, k0 = (t & 31) * 4;
        unsigned short hi[4], lo[4];
#pragma unroll
        for (int i = 0; i < 4; i++) {
            float v = W1[(k0 + i) * HIDF + n];
            __half h = __float2half_rn(v);
            hi[i] = __half_as_ushort(h);
            lo[i] = __half_as_ushort(__float2half_rn(v - __half2float(h)));
        }
        *(uint2*)&g_Bh[n * INF + k0] =
            make_uint2((uint32_t)hi[1] << 16 | hi[0], (uint32_t)hi[3] << 16 | hi[2]);
        *(uint2*)&g_Bl[n * INF + k0] =
            make_uint2((uint32_t)lo[1] << 16 | lo[0], (uint32_t)lo[3] << 16 | lo[2]);
    } else if (t < 8192 + 2560) {           // W2: n = u>>6 (40), k0 = (u&63)*4
        int u = t - 8192;
        int n = u >> 6, k0 = (u & 63) * 4;
        unsigned short hi[4], lo[4];
#pragma unroll
        for (int i = 0; i < 4; i++) {
            float v = W2[(k0 + i) * CLSF + n];
            __half h = __float2half_rn(v);
            hi[i] = __half_as_ushort(h);
            lo[i] = __half_as_ushort(__float2half_rn(v - __half2float(h)));
        }
        *(uint2*)&g_W2h[n * W2LD + k0] =
            make_uint2((uint32_t)hi[1] << 16 | hi[0], (uint32_t)hi[3] << 16 | hi[2]);
        *(uint2*)&g_W2l[n * W2LD + k0] =
            make_uint2((uint32_t)lo[1] << 16 | lo[0], (uint32_t)lo[3] << 16 | lo[2]);
    }
}

// ---------------- fused GEMM1+GEMM2 via fp16 mma.sync (2-pass) ----------------
#define SA   0                   // 128 x 272B = 34816
#define SB_H 34816
#define SB_L 69632
#define SW2H 104448              // 48*264*2 = 25344 B
#define SW2L 129792
#define SM_TOT 155136

__device__ __forceinline__ uint32_t smem_u32(const void* p) {
    uint32_t a;
    asm("{ .reg .u64 t; cvta.to.shared.u64 t, %1; cvt.u32.u64 %0, t; }" : "=r"(a) : "l"(p));
    return a;
}
#define LDSM4(R, addr) \
    asm volatile("ldmatrix.sync.aligned.m8n8.x4.shared.b16 {%0,%1,%2,%3}, [%4];" \
        : "=r"((R)[0]), "=r"((R)[1]), "=r"((R)[2]), "=r"((R)[3]) : "r"(addr))
#define MMAF16(C, A, B0, B1) \
    asm volatile("mma.sync.aligned.m16n8k16.row.col.f32.f16.f16.f32 " \
        "{%0,%1,%2,%3},{%4,%5,%6,%7},{%8,%9},{%0,%1,%2,%3};" \
        : "+f"((C)[0]), "+f"((C)[1]), "+f"((C)[2]), "+f"((C)[3]) \
        : "r"((A)[0]), "r"((A)[1]), "r"((A)[2]), "r"((A)[3]), "r"(B0), "r"(B1))

__device__ __forceinline__ uint32_t packh2(float a, float b) {
    __half2 h = __floats2half2_rn(a, b);
    return *(uint32_t*)&h;
}

__global__ void __launch_bounds__(256, 1) gemm1_fused(const float* __restrict__ b1) {
    extern __shared__ char sm[];
    int tid = threadIdx.x;
    int m0 = blockIdx.x * 128, n0 = blockIdx.y * 128;

    // ---- copy A (pre-converted fp16, pure bulk copy) ----
    {
        const uint4* sA = (const uint4*)(g_Ah + (size_t)m0 * INF);
#pragma unroll
        for (int i = 0; i < 8; i++) {
            int idx = tid + i * 256;            // 0..2047 uint4
            int row = idx >> 4, c = idx & 15;
            *(uint4*)(sm + SA + row * 272 + c * 16) = sA[idx];
        }
    }
    // ---- copy B (W1^T) hi/lo tiles ----
    {
        int nn = tid >> 1, half = tid & 1;
        const uint4* shh = (const uint4*)&g_Bh[(n0 + nn) * INF + half * 64];
        const uint4* sll = (const uint4*)&g_Bl[(n0 + nn) * INF + half * 64];
        uint4* dh = (uint4*)(sm + SB_H + nn * 272 + half * 128);
        uint4* dl = (uint4*)(sm + SB_L + nn * 272 + half * 128);
#pragma unroll
        for (int i = 0; i < 8; i++) { dh[i] = shh[i]; dl[i] = sll[i]; }
    }
    // ---- copy W2^T hi/lo ----
    {
        const uint4* sh = (const uint4*)g_W2h;
        const uint4* sl = (const uint4*)g_W2l;
        uint4* dh = (uint4*)(sm + SW2H);
        uint4* dl = (uint4*)(sm + SW2L);
#pragma unroll
        for (int i = 0; i < 7; i++) {
            int idx = tid + i * 256;
            if (idx < (W2N * W2LD * 2) / 16) { dh[idx] = sh[idx]; dl[idx] = sl[idx]; }
        }
    }
    __syncthreads();

    int lane = tid & 31, w = tid >> 5;
    int wm = (w & 3) * 32, wn = (w >> 2) * 64;
    uint32_t sb = smem_u32(sm);

    uint32_t aRow = (uint32_t)(wm + (lane & 15));
    uint32_t aK   = (uint32_t)((lane >> 4) * 8);
    uint32_t aOff = sb + SA + aRow * 272 + aK * 2;
    uint32_t bRow = (uint32_t)(wn + (lane & 7) + ((lane >> 4) & 1) * 8);
    uint32_t bK   = (uint32_t)(((lane >> 3) & 1) * 8);
    uint32_t bOffH = sb + SB_H + bRow * 272 + bK * 2;
    uint32_t bOffL = sb + SB_L + bRow * 272 + bK * 2;

    float acc[2][8][4];
#pragma unroll
    for (int a = 0; a < 2; a++)
#pragma unroll
        for (int b = 0; b < 8; b++)
#pragma unroll
            for (int c = 0; c < 4; c++) acc[a][b][c] = 0.f;

#pragma unroll
    for (int ks = 0; ks < 8; ks++) {
        uint32_t k2 = (uint32_t)(ks * 32);
        uint32_t Aa[2][4], Bh[4][4], Bl[4][4];
        LDSM4(Aa[0], aOff + k2);
        LDSM4(Aa[1], aOff + k2 + 16 * 272);
#pragma unroll
        for (int p = 0; p < 4; p++) {
            LDSM4(Bh[p], bOffH + k2 + p * 16 * 272);
            LDSM4(Bl[p], bOffL + k2 + p * 16 * 272);
        }
#pragma unroll
        for (int mf = 0; mf < 2; mf++) {
#pragma unroll
            for (int nf = 0; nf < 8; nf++) {
                int p = nf >> 1, s = (nf & 1) * 2;
                MMAF16(acc[mf][nf], Aa[mf], Bh[p][s], Bh[p][s + 1]);   // A @ Bh
                MMAF16(acc[mf][nf], Aa[mf], Bl[p][s], Bl[p][s + 1]);   // A @ Bl
            }
        }
    }

    // ---- bias + relu in registers ----
    int t = lane & 3;
#pragma unroll
    for (int nf = 0; nf < 8; nf++) {
        int col = n0 + wn + nf * 8 + t * 2;
        float2 bb = *(const float2*)&b1[col];
#pragma unroll
        for (int mf = 0; mf < 2; mf++) {
            acc[mf][nf][0] = fmaxf(acc[mf][nf][0] + bb.x, 0.f);
            acc[mf][nf][1] = fmaxf(acc[mf][nf][1] + bb.y, 0.f);
            acc[mf][nf][2] = fmaxf(acc[mf][nf][2] + bb.x, 0.f);
            acc[mf][nf][3] = fmaxf(acc[mf][nf][3] + bb.y, 0.f);
        }
    }

    // ---- gemm2: z(fp16) @ (W2h + W2l), k-slice = warp's 64 cols ----
    float oacc[2][5][4];
#pragma unroll
    for (int a = 0; a < 2; a++)
#pragma unroll
        for (int b = 0; b < 5; b++)
#pragma unroll
            for (int c = 0; c < 4; c++) oacc[a][b][c] = 0.f;

    uint32_t w2row = (uint32_t)((lane & 7) + ((lane >> 4) & 1) * 8);
    uint32_t w2kh  = (uint32_t)(((lane >> 3) & 1) * 16);
    uint32_t w2baseH = sb + SW2H + w2row * (W2LD * 2) + w2kh;
    uint32_t w2baseL = sb + SW2L + w2row * (W2LD * 2) + w2kh;

#pragma unroll
    for (int c = 0; c < 4; c++) {
        uint32_t kb = (uint32_t)((n0 + wn + 16 * c) * 2);
        uint32_t Bqh[3][4], Bql[3][4];
#pragma unroll
        for (int p = 0; p < 3; p++) {
            LDSM4(Bqh[p], w2baseH + p * 16 * (W2LD * 2) + kb);
            LDSM4(Bql[p], w2baseL + p * 16 * (W2LD * 2) + kb);
        }
#pragma unroll
        for (int mf = 0; mf < 2; mf++) {
            uint32_t za[4];
            za[0] = packh2(acc[mf][2 * c][0],     acc[mf][2 * c][1]);
            za[1] = packh2(acc[mf][2 * c][2],     acc[mf][2 * c][3]);
            za[2] = packh2(acc[mf][2 * c + 1][0], acc[mf][2 * c + 1][1]);
            za[3] = packh2(acc[mf][2 * c + 1][2], acc[mf][2 * c + 1][3]);
#pragma unroll
            for (int o = 0; o < 5; o++) {
                int p = o >> 1, s = (o & 1) * 2;
                MMAF16(oacc[mf][o], za, Bqh[p][s], Bqh[p][s + 1]);   // z @ Wh
                MMAF16(oacc[mf][o], za, Bql[p][s], Bql[p][s + 1]);   // z @ Wl
            }
        }
    }

    // ---- write partials ----
    int bufid = blockIdx.y * 2 + (w >> 2);
    int g = lane >> 2;
    float* part = g_part[bufid];
#pragma unroll
    for (int mf = 0; mf < 2; mf++) {
        int r0 = m0 + wm + mf * 16 + g;
        int r1 = r0 + 8;
#pragma unroll
        for (int o = 0; o < 5; o++) {
            int col = o * 8 + t * 2;
            if (r0 < Nn) *(float2*)&part[(size_t)r0 * CLSF + col] =
                make_float2(oacc[mf][o][0], oacc[mf][o][1]);
            if (r1 < Nn) *(float2*)&part[(size_t)r1 * CLSF + col] =
                make_float2(oacc[mf][o][2], oacc[mf][o][3]);
        }
    }
}

// ---------------- combine: out = sum(parts) + b2 ----------------
__global__ void combine_k(const float* __restrict__ b2, float* __restrict__ out) {
    int i = blockIdx.x * 256 + threadIdx.x;      // float2 index
    if (i >= Nn * CLSF / 2) return;
    const float2* p0 = (const float2*)g_part[0];
    const float2* p1 = (const float2*)g_part[1];
    const float2* p2 = (const float2*)g_part[2];
    const float2* p3 = (const float2*)g_part[3];
    float2 a = p0[i], b = p1[i], c = p2[i], d = p3[i];
    int col2 = i % (CLSF / 2);
    float2 bb = *(const float2*)&b2[col2 * 2];
    float2 o;
    o.x = a.x + b.x + c.x + d.x + bb.x;
    o.y = a.y + b.y + c.y + d.y + bb.y;
    ((float2*)out)[i] = o;
}

extern "C" void kernel_launch(void* const* d_in, const int* in_sizes, int n_in,
                              void* d_out, int out_size) {
    const float* features = (const float*)d_in[0];
    const int*   src      = (const int*)d_in[1];
    const int*   dst      = (const int*)d_in[2];
    const float* W1       = (const float*)d_in[3];
    const float* b1       = (const float*)d_in[4];
    const float* W2       = (const float*)d_in[5];
    const float* b2       = (const float*)d_in[6];
    float*       out      = (float*)d_out;

    cudaFuncSetAttribute(gemm1_fused, cudaFuncAttributeMaxDynamicSharedMemorySize, SM_TOT);

    zero_deg_k<<<(Nn + 255) / 256, 256>>>();
    hist_k<<<(Ee + 255) / 256, 256>>>(dst);
    prepW_k<<<42, 256>>>(W1, W2);
    bsum_k<<<SBLK, 256>>>();
    bscan_k<<<1, 256>>>();
    fill_k<<<SBLK, 256>>>();
    permute_k<<<(Ee + 255) / 256, 256>>>(src, dst);

    gather1_k<<<Nn / 8, 256>>>((const float4*)features);
    gather2_k<<<Nn / 8, 256>>>();

    gemm1_fused<<<dim3(MTILES, 2), 256, SM_TOT>>>(b1);
    combine_k<<<(Nn * CLSF / 2 + 255) / 256, 256>>>(b2, out);
}

// round 12
// speedup vs baseline: 2.7141x; 1.0881x over previous
#include <cuda_runtime.h>
#include <cuda_fp16.h>
#include <cstdint>

#define Nn   40000
#define Ee   640000
#define INF  128
#define HIDF 256
#define CLSF 40
#define MTILES 313
#define MPAD  (MTILES * 128)     // 40064
#define SBLK  157                // ceil(40000/256)
#define W2N   48                 // padded n for W2^T
#define W2LD  264                // padded k stride (528B rows)

// ---- scratch (device globals; zero-initialized at load) ----
__device__ int    g_deg[Nn];
__device__ int    g_row[Nn + 1];
__device__ int    g_cur[Nn];
__device__ int    g_esrc[Ee];
__device__ int    g_bsum[SBLK];
__device__ int    g_boff[SBLK];
__device__ float  g_norm[Nn];
__device__ float  g_norm2[Nn];
__device__ __align__(16) __half g_Xs[Nn * INF];             // norm.*X fp16
__device__ __align__(16) __half g_T[Nn * INF];              // norm2.*(A Xs) fp16
__device__ __align__(16) __half g_Ah[MPAD * INF];           // norm.*(A T) fp16, pad rows 0
__device__ __align__(16) unsigned short g_Bh[HIDF * INF];   // W1^T fp16 hi, [n][k]
__device__ __align__(16) unsigned short g_Bl[HIDF * INF];   // W1^T fp16 lo
__device__ __align__(16) unsigned short g_W2h[W2N * W2LD];  // W2^T fp16 hi
__device__ __align__(16) unsigned short g_W2l[W2N * W2LD];  // W2^T fp16 lo
__device__ float  g_part[4][Nn * CLSF];                     // gemm2 partials

// ---------------- degree / CSR build ----------------
__global__ void zero_deg_k() {
    int i = blockIdx.x * blockDim.x + threadIdx.x;
    if (i < Nn) g_deg[i] = 0;
}
__global__ void hist_k(const int* __restrict__ dst) {
    int i = blockIdx.x * blockDim.x + threadIdx.x;
    if (i < Ee) atomicAdd(&g_deg[dst[i]], 1);
}

// ---- parallel hierarchical scan ----
__global__ void bsum_k() {
    __shared__ int ws[8];
    int i = blockIdx.x * 256 + threadIdx.x;
    int v = (i < Nn) ? g_deg[i] : 0;
#pragma unroll
    for (int o = 16; o > 0; o >>= 1) v += __shfl_down_sync(0xffffffffu, v, o);
    int lane = threadIdx.x & 31, w = threadIdx.x >> 5;
    if (lane == 0) ws[w] = v;
    __syncthreads();
    if (w == 0) {
        int s = (lane < 8) ? ws[lane] : 0;
#pragma unroll
        for (int o = 4; o > 0; o >>= 1) s += __shfl_down_sync(0xffffffffu, s, o);
        if (lane == 0) g_bsum[blockIdx.x] = s;
    }
}
__global__ void bscan_k() {
    __shared__ int ws[8];
    int t = threadIdx.x;
    int v = (t < SBLK) ? g_bsum[t] : 0;
    int lane = t & 31, w = t >> 5;
    int inc = v;
#pragma unroll
    for (int o = 1; o < 32; o <<= 1) {
        int n = __shfl_up_sync(0xffffffffu, inc, o);
        if (lane >= o) inc += n;
    }
    if (lane == 31) ws[w] = inc;
    __syncthreads();
    if (w == 0) {
        int s = (lane < 8) ? ws[lane] : 0;
        int si = s;
#pragma unroll
        for (int o = 1; o < 8; o <<= 1) {
            int n = __shfl_up_sync(0xffffffffu, si, o);
            if (lane >= o) si += n;
        }
        if (lane < 8) ws[lane] = si - s;
    }
    __syncthreads();
    if (t < SBLK) g_boff[t] = ws[w] + inc - v;
}
__global__ void fill_k() {
    __shared__ int ws[8];
    int i = blockIdx.x * 256 + threadIdx.x;
    int lane = threadIdx.x & 31, w = threadIdx.x >> 5;
    int d = (i < Nn) ? g_deg[i] : 0;
    int inc = d;
#pragma unroll
    for (int o = 1; o < 32; o <<= 1) {
        int n = __shfl_up_sync(0xffffffffu, inc, o);
        if (lane >= o) inc += n;
    }
    if (lane == 31) ws[w] = inc;
    __syncthreads();
    if (w == 0) {
        int s = (lane < 8) ? ws[lane] : 0;
        int si = s;
#pragma unroll
        for (int o = 1; o < 8; o <<= 1) {
            int n = __shfl_up_sync(0xffffffffu, si, o);
            if (lane >= o) si += n;
        }
        if (lane < 8) ws[lane] = si - s;
    }
    __syncthreads();
    if (i < Nn) {
        int off = g_boff[blockIdx.x] + ws[w] + inc - d;
        g_row[i] = off;
        g_cur[i] = off;
        float nm = rsqrtf(fmaxf((float)d, 1.0f));
        g_norm[i] = nm;
        g_norm2[i] = nm * nm;
    }
}

__global__ void permute_k(const int* __restrict__ src, const int* __restrict__ dst) {
    int i = blockIdx.x * blockDim.x + threadIdx.x;
    if (i < Ee) { int d = dst[i]; int p = atomicAdd(&g_cur[d], 1); g_esrc[p] = src[i]; }
}

// ---- Xs[v] = norm[v] * X[v] in fp16 ----
__global__ void prepX_k(const float4* __restrict__ xin) {
    int t = blockIdx.x * 256 + threadIdx.x;      // 0 .. Nn*32-1
    if (t >= Nn * 32) return;
    int v = t >> 5;
    float nm = g_norm[v];
    float4 x = xin[t];
    __half2 p0 = __floats2half2_rn(x.x * nm, x.y * nm);
    __half2 p1 = __floats2half2_rn(x.z * nm, x.w * nm);
    uint2 pk;
    pk.x = *(uint32_t*)&p0;
    pk.y = *(uint32_t*)&p1;
    ((uint2*)g_Xs)[t] = pk;
}

// ---- hop1: T[v] = norm2[v] * sum Xs[src] ----
__global__ void gather1_k() {
    int w = (blockIdx.x * blockDim.x + threadIdx.x) >> 5;
    int lane = threadIdx.x & 31;
    if (w >= Nn) return;
    int beg = g_row[w], end = beg + g_deg[w];
    const uint2* rows = (const uint2*)g_Xs;
    float a0 = 0.f, a1 = 0.f, a2 = 0.f, a3 = 0.f;
    int e = beg;
    for (; e + 3 < end; e += 4) {
        int s0 = g_esrc[e], s1 = g_esrc[e + 1], s2 = g_esrc[e + 2], s3 = g_esrc[e + 3];
        uint2 p0 = rows[s0 * 32 + lane], p1 = rows[s1 * 32 + lane];
        uint2 p2 = rows[s2 * 32 + lane], p3 = rows[s3 * 32 + lane];
        float2 f;
        f = __half22float2(*(__half2*)&p0.x); a0 += f.x; a1 += f.y;
        f = __half22float2(*(__half2*)&p0.y); a2 += f.x; a3 += f.y;
        f = __half22float2(*(__half2*)&p1.x); a0 += f.x; a1 += f.y;
        f = __half22float2(*(__half2*)&p1.y); a2 += f.x; a3 += f.y;
        f = __half22float2(*(__half2*)&p2.x); a0 += f.x; a1 += f.y;
        f = __half22float2(*(__half2*)&p2.y); a2 += f.x; a3 += f.y;
        f = __half22float2(*(__half2*)&p3.x); a0 += f.x; a1 += f.y;
        f = __half22float2(*(__half2*)&p3.y); a2 += f.x; a3 += f.y;
    }
    for (; e < end; e++) {
        int s0 = g_esrc[e];
        uint2 p0 = rows[s0 * 32 + lane];
        float2 f;
        f = __half22float2(*(__half2*)&p0.x); a0 += f.x; a1 += f.y;
        f = __half22float2(*(__half2*)&p0.y); a2 += f.x; a3 += f.y;
    }
    float n2 = g_norm2[w];
    __half2 q0 = __floats2half2_rn(a0 * n2, a1 * n2);
    __half2 q1 = __floats2half2_rn(a2 * n2, a3 * n2);
    uint2 o;
    o.x = *(uint32_t*)&q0;
    o.y = *(uint32_t*)&q1;
    ((uint2*)g_T)[w * 32 + lane] = o;
}

// ---- hop2: Ah[v] = norm[v] * sum T[src] ----
__global__ void gather2_k() {
    int w = (blockIdx.x * blockDim.x + threadIdx.x) >> 5;
    int lane = threadIdx.x & 31;
    if (w >= Nn) return;
    int beg = g_row[w], end = beg + g_deg[w];
    const uint2* rows = (const uint2*)g_T;
    float a0 = 0.f, a1 = 0.f, a2 = 0.f, a3 = 0.f;
    int e = beg;
    for (; e + 3 < end; e += 4) {
        int s0 = g_esrc[e], s1 = g_esrc[e + 1], s2 = g_esrc[e + 2], s3 = g_esrc[e + 3];
        uint2 p0 = rows[s0 * 32 + lane], p1 = rows[s1 * 32 + lane];
        uint2 p2 = rows[s2 * 32 + lane], p3 = rows[s3 * 32 + lane];
        float2 f;
        f = __half22float2(*(__half2*)&p0.x); a0 += f.x; a1 += f.y;
        f = __half22float2(*(__half2*)&p0.y); a2 += f.x; a3 += f.y;
        f = __half22float2(*(__half2*)&p1.x); a0 += f.x; a1 += f.y;
        f = __half22float2(*(__half2*)&p1.y); a2 += f.x; a3 += f.y;
        f = __half22float2(*(__half2*)&p2.x); a0 += f.x; a1 += f.y;
        f = __half22float2(*(__half2*)&p2.y); a2 += f.x; a3 += f.y;
        f = __half22float2(*(__half2*)&p3.x); a0 += f.x; a1 += f.y;
        f = __half22float2(*(__half2*)&p3.y); a2 += f.x; a3 += f.y;
    }
    for (; e < end; e++) {
        int s0 = g_esrc[e];
        uint2 p0 = rows[s0 * 32 + lane];
        float2 f;
        f = __half22float2(*(__half2*)&p0.x); a0 += f.x; a1 += f.y;
        f = __half22float2(*(__half2*)&p0.y); a2 += f.x; a3 += f.y;
    }
    float nw = g_norm[w];
    __half2 q0 = __floats2half2_rn(a0 * nw, a1 * nw);
    __half2 q1 = __floats2half2_rn(a2 * nw, a3 * nw);
    uint2 o;
    o.x = *(uint32_t*)&q0;
    o.y = *(uint32_t*)&q1;
    ((uint2*)g_Ah)[w * 32 + lane] = o;
}

// ---- weight prep: W1^T and W2^T, fp16 hi/lo split ----
__global__ void prepW_k(const float* __restrict__ W1, const float* __restrict__ W2) {
    int t = blockIdx.x * blockDim.x + threadIdx.x;
    if (t < 8192) {                         // W1
        int n = t >> 5, k0 = (t & 31) * 4;
        unsigned short hi[4], lo[4];
#pragma unroll
        for (int i = 0; i < 4; i++) {
            float v = W1[(k0 + i) * HIDF + n];
            __half h = __float2half_rn(v);
            hi[i] = __half_as_ushort(h);
            lo[i] = __half_as_ushort(__float2half_rn(v - __half2float(h)));
        }
        *(uint2*)&g_Bh[n * INF + k0] =
            make_uint2((uint32_t)hi[1] << 16 | hi[0], (uint32_t)hi[3] << 16 | hi[2]);
        *(uint2*)&g_Bl[n * INF + k0] =
            make_uint2((uint32_t)lo[1] << 16 | lo[0], (uint32_t)lo[3] << 16 | lo[2]);
    } else if (t < 8192 + 2560) {           // W2
        int u = t - 8192;
        int n = u >> 6, k0 = (u & 63) * 4;
        unsigned short hi[4], lo[4];
#pragma unroll
        for (int i = 0; i < 4; i++) {
            float v = W2[(k0 + i) * CLSF + n];
            __half h = __float2half_rn(v);
            hi[i] = __half_as_ushort(h);
            lo[i] = __half_as_ushort(__float2half_rn(v - __half2float(h)));
        }
        *(uint2*)&g_W2h[n * W2LD + k0] =
            make_uint2((uint32_t)hi[1] << 16 | hi[0], (uint32_t)hi[3] << 16 | hi[2]);
        *(uint2*)&g_W2l[n * W2LD + k0] =
            make_uint2((uint32_t)lo[1] << 16 | lo[0], (uint32_t)lo[3] << 16 | lo[2]);
    }
}

// ---------------- fused GEMM1+GEMM2 via fp16 mma.sync (2-pass) ----------------
#define SA   0                   // 128 x 272B = 34816
#define SB_H 34816
#define SB_L 69632
#define SW2H 104448              // 48*264*2 = 25344 B
#define SW2L 129792
#define SM_TOT 155136

__device__ __forceinline__ uint32_t smem_u32(const void* p) {
    uint32_t a;
    asm("{ .reg .u64 t; cvta.to.shared.u64 t, %1; cvt.u32.u64 %0, t; }" : "=r"(a) : "l"(p));
    return a;
}
#define LDSM4(R, addr) \
    asm volatile("ldmatrix.sync.aligned.m8n8.x4.shared.b16 {%0,%1,%2,%3}, [%4];" \
        : "=r"((R)[0]), "=r"((R)[1]), "=r"((R)[2]), "=r"((R)[3]) : "r"(addr))
#define MMAF16(C, A, B0, B1) \
    asm volatile("mma.sync.aligned.m16n8k16.row.col.f32.f16.f16.f32 " \
        "{%0,%1,%2,%3},{%4,%5,%6,%7},{%8,%9},{%0,%1,%2,%3};" \
        : "+f"((C)[0]), "+f"((C)[1]), "+f"((C)[2]), "+f"((C)[3]) \
        : "r"((A)[0]), "r"((A)[1]), "r"((A)[2]), "r"((A)[3]), "r"(B0), "r"(B1))

__device__ __forceinline__ uint32_t packh2(float a, float b) {
    __half2 h = __floats2half2_rn(a, b);
    return *(uint32_t*)&h;
}

__global__ void __launch_bounds__(256, 1) gemm1_fused(const float* __restrict__ b1) {
    extern __shared__ char sm[];
    int tid = threadIdx.x;
    int m0 = blockIdx.x * 128, n0 = blockIdx.y * 128;

    // ---- copy A (pre-converted fp16, pure bulk copy) ----
    {
        const uint4* sA = (const uint4*)(g_Ah + (size_t)m0 * INF);
#pragma unroll
        for (int i = 0; i < 8; i++) {
            int idx = tid + i * 256;            // 0..2047 uint4
            int row = idx >> 4, c = idx & 15;
            *(uint4*)(sm + SA + row * 272 + c * 16) = sA[idx];
        }
    }
    // ---- copy B (W1^T) hi/lo tiles ----
    {
        int nn = tid >> 1, half = tid & 1;
        const uint4* shh = (const uint4*)&g_Bh[(n0 + nn) * INF + half * 64];
        const uint4* sll = (const uint4*)&g_Bl[(n0 + nn) * INF + half * 64];
        uint4* dh = (uint4*)(sm + SB_H + nn * 272 + half * 128);
        uint4* dl = (uint4*)(sm + SB_L + nn * 272 + half * 128);
#pragma unroll
        for (int i = 0; i < 8; i++) { dh[i] = shh[i]; dl[i] = sll[i]; }
    }
    // ---- copy W2^T hi/lo ----
    {
        const uint4* sh = (const uint4*)g_W2h;
        const uint4* sl = (const uint4*)g_W2l;
        uint4* dh = (uint4*)(sm + SW2H);
        uint4* dl = (uint4*)(sm + SW2L);
#pragma unroll
        for (int i = 0; i < 7; i++) {
            int idx = tid + i * 256;
            if (idx < (W2N * W2LD * 2) / 16) { dh[idx] = sh[idx]; dl[idx] = sl[idx]; }
        }
    }
    __syncthreads();

    int lane = tid & 31, w = tid >> 5;
    int wm = (w & 3) * 32, wn = (w >> 2) * 64;
    uint32_t sb = smem_u32(sm);

    uint32_t aRow = (uint32_t)(wm + (lane & 15));
    uint32_t aK   = (uint32_t)((lane >> 4) * 8);
    uint32_t aOff = sb + SA + aRow * 272 + aK * 2;
    uint32_t bRow = (uint32_t)(wn + (lane & 7) + ((lane >> 4) & 1) * 8);
    uint32_t bK   = (uint32_t)(((lane >> 3) & 1) * 8);
    uint32_t bOffH = sb + SB_H + bRow * 272 + bK * 2;
    uint32_t bOffL = sb + SB_L + bRow * 272 + bK * 2;

    float acc[2][8][4];
#pragma unroll
    for (int a = 0; a < 2; a++)
#pragma unroll
        for (int b = 0; b < 8; b++)
#pragma unroll
            for (int c = 0; c < 4; c++) acc[a][b][c] = 0.f;

#pragma unroll
    for (int ks = 0; ks < 8; ks++) {
        uint32_t k2 = (uint32_t)(ks * 32);
        uint32_t Aa[2][4], Bh[4][4], Bl[4][4];
        LDSM4(Aa[0], aOff + k2);
        LDSM4(Aa[1], aOff + k2 + 16 * 272);
#pragma unroll
        for (int p = 0; p < 4; p++) {
            LDSM4(Bh[p], bOffH + k2 + p * 16 * 272);
            LDSM4(Bl[p], bOffL + k2 + p * 16 * 272);
        }
#pragma unroll
        for (int mf = 0; mf < 2; mf++) {
#pragma unroll
            for (int nf = 0; nf < 8; nf++) {
                int p = nf >> 1, s = (nf & 1) * 2;
                MMAF16(acc[mf][nf], Aa[mf], Bh[p][s], Bh[p][s + 1]);   // A @ Bh
                MMAF16(acc[mf][nf], Aa[mf], Bl[p][s], Bl[p][s + 1]);   // A @ Bl
            }
        }
    }

    // ---- bias + relu in registers ----
    int t = lane & 3;
#pragma unroll
    for (int nf = 0; nf < 8; nf++) {
        int col = n0 + wn + nf * 8 + t * 2;
        float2 bb = *(const float2*)&b1[col];
#pragma unroll
        for (int mf = 0; mf < 2; mf++) {
            acc[mf][nf][0] = fmaxf(acc[mf][nf][0] + bb.x, 0.f);
            acc[mf][nf][1] = fmaxf(acc[mf][nf][1] + bb.y, 0.f);
            acc[mf][nf][2] = fmaxf(acc[mf][nf][2] + bb.x, 0.f);
            acc[mf][nf][3] = fmaxf(acc[mf][nf][3] + bb.y, 0.f);
        }
    }

    // ---- gemm2: z(fp16) @ (W2h + W2l), k-slice = warp's 64 cols ----
    float oacc[2][5][4];
#pragma unroll
    for (int a = 0; a < 2; a++)
#pragma unroll
        for (int b = 0; b < 5; b++)
#pragma unroll
            for (int c = 0; c < 4; c++) oacc[a][b][c] = 0.f;

    uint32_t w2row = (uint32_t)((lane & 7) + ((lane >> 4) & 1) * 8);
    uint32_t w2kh  = (uint32_t)(((lane >> 3) & 1) * 16);
    uint32_t w2baseH = sb + SW2H + w2row * (W2LD * 2) + w2kh;
    uint32_t w2baseL = sb + SW2L + w2row * (W2LD * 2) + w2kh;

#pragma unroll
    for (int c = 0; c < 4; c++) {
        uint32_t kb = (uint32_t)((n0 + wn + 16 * c) * 2);
        uint32_t Bqh[3][4], Bql[3][4];
#pragma unroll
        for (int p = 0; p < 3; p++) {
            LDSM4(Bqh[p], w2baseH + p * 16 * (W2LD * 2) + kb);
            LDSM4(Bql[p], w2baseL + p * 16 * (W2LD * 2) + kb);
        }
#pragma unroll
        for (int mf = 0; mf < 2; mf++) {
            uint32_t za[4];
            za[0] = packh2(acc[mf][2 * c][0],     acc[mf][2 * c][1]);
            za[1] = packh2(acc[mf][2 * c][2],     acc[mf][2 * c][3]);
            za[2] = packh2(acc[mf][2 * c + 1][0], acc[mf][2 * c + 1][1]);
            za[3] = packh2(acc[mf][2 * c + 1][2], acc[mf][2 * c + 1][3]);
#pragma unroll
            for (int o = 0; o < 5; o++) {
                int p = o >> 1, s = (o & 1) * 2;
                MMAF16(oacc[mf][o], za, Bqh[p][s], Bqh[p][s + 1]);   // z @ Wh
                MMAF16(oacc[mf][o], za, Bql[p][s], Bql[p][s + 1]);   // z @ Wl
            }
        }
    }

    // ---- write partials ----
    int bufid = blockIdx.y * 2 + (w >> 2);
    int g = lane >> 2;
    float* part = g_part[bufid];
#pragma unroll
    for (int mf = 0; mf < 2; mf++) {
        int r0 = m0 + wm + mf * 16 + g;
        int r1 = r0 + 8;
#pragma unroll
        for (int o = 0; o < 5; o++) {
            int col = o * 8 + t * 2;
            if (r0 < Nn) *(float2*)&part[(size_t)r0 * CLSF + col] =
                make_float2(oacc[mf][o][0], oacc[mf][o][1]);
            if (r1 < Nn) *(float2*)&part[(size_t)r1 * CLSF + col] =
                make_float2(oacc[mf][o][2], oacc[mf][o][3]);
        }
    }
}

// ---------------- combine: out = sum(parts) + b2 ----------------
__global__ void combine_k(const float* __restrict__ b2, float* __restrict__ out) {
    int i = blockIdx.x * 256 + threadIdx.x;      // float2 index
    if (i >= Nn * CLSF / 2) return;
    const float2* p0 = (const float2*)g_part[0];
    const float2* p1 = (const float2*)g_part[1];
    const float2* p2 = (const float2*)g_part[2];
    const float2* p3 = (const float2*)g_part[3];
    float2 a = p0[i], b = p1[i], c = p2[i], d = p3[i];
    int col2 = i % (CLSF / 2);
    float2 bb = *(const float2*)&b2[col2 * 2];
    float2 o;
    o.x = a.x + b.x + c.x + d.x + bb.x;
    o.y = a.y + b.y + c.y + d.y + bb.y;
    ((float2*)out)[i] = o;
}

extern "C" void kernel_launch(void* const* d_in, const int* in_sizes, int n_in,
                              void* d_out, int out_size) {
    const float* features = (const float*)d_in[0];
    const int*   src      = (const int*)d_in[1];
    const int*   dst      = (const int*)d_in[2];
    const float* W1       = (const float*)d_in[3];
    const float* b1       = (const float*)d_in[4];
    const float* W2       = (const float*)d_in[5];
    const float* b2       = (const float*)d_in[6];
    float*       out      = (float*)d_out;

    cudaFuncSetAttribute(gemm1_fused, cudaFuncAttributeMaxDynamicSharedMemorySize, SM_TOT);

    zero_deg_k<<<(Nn + 255) / 256, 256>>>();
    hist_k<<<(Ee + 255) / 256, 256>>>(dst);
    prepW_k<<<42, 256>>>(W1, W2);
    bsum_k<<<SBLK, 256>>>();
    bscan_k<<<1, 256>>>();
    fill_k<<<SBLK, 256>>>();
    prepX_k<<<(Nn * 32 + 255) / 256, 256>>>((const float4*)features);
    permute_k<<<(Ee + 255) / 256, 256>>>(src, dst);

    gather1_k<<<Nn / 8, 256>>>();
    gather2_k<<<Nn / 8, 256>>>();

    gemm1_fused<<<dim3(MTILES, 2), 256, SM_TOT>>>(b1);
    combine_k<<<(Nn * CLSF / 2 + 255) / 256, 256>>>(b2, out);
}

// round 13
// speedup vs baseline: 3.3377x; 1.2298x over previous
#include <cuda_runtime.h>
#include <cuda_fp16.h>
#include <cstdint>

#define Nn   40000
#define Ee   640000
#define INF  128
#define HIDF 256
#define CLSF 40
#define MTILES 313
#define MPAD  (MTILES * 128)     // 40064
#define SBLK  157                // ceil(40000/256)
#define W2N   48                 // padded n for W2^T
#define W2LD  264                // padded k stride (528B rows)

// ---- scratch (device globals; zero-initialized at load) ----
__device__ int    g_deg[Nn];
__device__ int    g_row[Nn + 1];
__device__ int    g_cur[Nn];
__device__ int    g_esrc[Ee];
__device__ int    g_bsum[SBLK];
__device__ int    g_boff[SBLK];
__device__ float  g_norm[Nn];
__device__ float  g_norm2[Nn];
__device__ __align__(16) __half g_Xs[Nn * INF];             // norm.*X fp16
__device__ __align__(16) __half g_T[Nn * INF];              // norm2.*(A Xs) fp16
__device__ __align__(16) __half g_Ah[MPAD * INF];           // norm.*(A T) fp16, pad rows 0
__device__ __align__(16) unsigned short g_Bh[HIDF * INF];   // W1^T fp16, [n][k]
__device__ __align__(16) unsigned short g_W2h[W2N * W2LD];  // W2^T fp16
__device__ float  g_part[4][Nn * CLSF];                     // gemm2 partials

// ---------------- init: zero deg + weight prep (fp16 single) ----------------
__global__ void init_k(const float* __restrict__ W1, const float* __restrict__ W2) {
    int t = blockIdx.x * 256 + threadIdx.x;
    if (t < Nn) g_deg[t] = 0;
    if (t < 8192) {                         // W1: n = t>>5 (256), k0 = (t&31)*4
        int n = t >> 5, k0 = (t & 31) * 4;
        unsigned short h[4];
#pragma unroll
        for (int i = 0; i < 4; i++)
            h[i] = __half_as_ushort(__float2half_rn(W1[(k0 + i) * HIDF + n]));
        *(uint2*)&g_Bh[n * INF + k0] =
            make_uint2((uint32_t)h[1] << 16 | h[0], (uint32_t)h[3] << 16 | h[2]);
    } else if (t < 8192 + 2560) {           // W2: n = u>>6 (40), k0 = (u&63)*4
        int u = t - 8192;
        int n = u >> 6, k0 = (u & 63) * 4;
        unsigned short h[4];
#pragma unroll
        for (int i = 0; i < 4; i++)
            h[i] = __half_as_ushort(__float2half_rn(W2[(k0 + i) * CLSF + n]));
        *(uint2*)&g_W2h[n * W2LD + k0] =
            make_uint2((uint32_t)h[1] << 16 | h[0], (uint32_t)h[3] << 16 | h[2]);
    }
}

__global__ void hist_k(const int* __restrict__ dst) {
    int i = blockIdx.x * blockDim.x + threadIdx.x;
    if (i < Ee) atomicAdd(&g_deg[dst[i]], 1);
}

// ---- parallel hierarchical scan ----
__global__ void bsum_k() {
    __shared__ int ws[8];
    int i = blockIdx.x * 256 + threadIdx.x;
    int v = (i < Nn) ? g_deg[i] : 0;
#pragma unroll
    for (int o = 16; o > 0; o >>= 1) v += __shfl_down_sync(0xffffffffu, v, o);
    int lane = threadIdx.x & 31, w = threadIdx.x >> 5;
    if (lane == 0) ws[w] = v;
    __syncthreads();
    if (w == 0) {
        int s = (lane < 8) ? ws[lane] : 0;
#pragma unroll
        for (int o = 4; o > 0; o >>= 1) s += __shfl_down_sync(0xffffffffu, s, o);
        if (lane == 0) g_bsum[blockIdx.x] = s;
    }
}
__global__ void bscan_k() {
    __shared__ int ws[8];
    int t = threadIdx.x;
    int v = (t < SBLK) ? g_bsum[t] : 0;
    int lane = t & 31, w = t >> 5;
    int inc = v;
#pragma unroll
    for (int o = 1; o < 32; o <<= 1) {
        int n = __shfl_up_sync(0xffffffffu, inc, o);
        if (lane >= o) inc += n;
    }
    if (lane == 31) ws[w] = inc;
    __syncthreads();
    if (w == 0) {
        int s = (lane < 8) ? ws[lane] : 0;
        int si = s;
#pragma unroll
        for (int o = 1; o < 8; o <<= 1) {
            int n = __shfl_up_sync(0xffffffffu, si, o);
            if (lane >= o) si += n;
        }
        if (lane < 8) ws[lane] = si - s;
    }
    __syncthreads();
    if (t < SBLK) g_boff[t] = ws[w] + inc - v;
}
__global__ void fill_k() {
    __shared__ int ws[8];
    int i = blockIdx.x * 256 + threadIdx.x;
    int lane = threadIdx.x & 31, w = threadIdx.x >> 5;
    int d = (i < Nn) ? g_deg[i] : 0;
    int inc = d;
#pragma unroll
    for (int o = 1; o < 32; o <<= 1) {
        int n = __shfl_up_sync(0xffffffffu, inc, o);
        if (lane >= o) inc += n;
    }
    if (lane == 31) ws[w] = inc;
    __syncthreads();
    if (w == 0) {
        int s = (lane < 8) ? ws[lane] : 0;
        int si = s;
#pragma unroll
        for (int o = 1; o < 8; o <<= 1) {
            int n = __shfl_up_sync(0xffffffffu, si, o);
            if (lane >= o) si += n;
        }
        if (lane < 8) ws[lane] = si - s;
    }
    __syncthreads();
    if (i < Nn) {
        int off = g_boff[blockIdx.x] + ws[w] + inc - d;
        g_row[i] = off;
        g_cur[i] = off;
        float nm = rsqrtf(fmaxf((float)d, 1.0f));
        g_norm[i] = nm;
        g_norm2[i] = nm * nm;
    }
}

__global__ void permute_k(const int* __restrict__ src, const int* __restrict__ dst) {
    int i = blockIdx.x * blockDim.x + threadIdx.x;
    if (i < Ee) { int d = dst[i]; int p = atomicAdd(&g_cur[d], 1); g_esrc[p] = src[i]; }
}

// ---- Xs[v] = norm[v] * X[v] in fp16 ----
__global__ void prepX_k(const float4* __restrict__ xin) {
    int t = blockIdx.x * 256 + threadIdx.x;      // 0 .. Nn*32-1
    if (t >= Nn * 32) return;
    int v = t >> 5;
    float nm = g_norm[v];
    float4 x = xin[t];
    __half2 p0 = __floats2half2_rn(x.x * nm, x.y * nm);
    __half2 p1 = __floats2half2_rn(x.z * nm, x.w * nm);
    uint2 pk;
    pk.x = *(uint32_t*)&p0;
    pk.y = *(uint32_t*)&p1;
    ((uint2*)g_Xs)[t] = pk;
}

// ---- hop1: T[v] = norm2[v] * sum Xs[src] ----
__global__ void gather1_k() {
    int w = (blockIdx.x * blockDim.x + threadIdx.x) >> 5;
    int lane = threadIdx.x & 31;
    if (w >= Nn) return;
    int beg = g_row[w], end = beg + g_deg[w];
    const uint2* rows = (const uint2*)g_Xs;
    float a0 = 0.f, a1 = 0.f, a2 = 0.f, a3 = 0.f;
    int e = beg;
    for (; e + 3 < end; e += 4) {
        int s0 = g_esrc[e], s1 = g_esrc[e + 1], s2 = g_esrc[e + 2], s3 = g_esrc[e + 3];
        uint2 p0 = rows[s0 * 32 + lane], p1 = rows[s1 * 32 + lane];
        uint2 p2 = rows[s2 * 32 + lane], p3 = rows[s3 * 32 + lane];
        float2 f;
        f = __half22float2(*(__half2*)&p0.x); a0 += f.x; a1 += f.y;
        f = __half22float2(*(__half2*)&p0.y); a2 += f.x; a3 += f.y;
        f = __half22float2(*(__half2*)&p1.x); a0 += f.x; a1 += f.y;
        f = __half22float2(*(__half2*)&p1.y); a2 += f.x; a3 += f.y;
        f = __half22float2(*(__half2*)&p2.x); a0 += f.x; a1 += f.y;
        f = __half22float2(*(__half2*)&p2.y); a2 += f.x; a3 += f.y;
        f = __half22float2(*(__half2*)&p3.x); a0 += f.x; a1 += f.y;
        f = __half22float2(*(__half2*)&p3.y); a2 += f.x; a3 += f.y;
    }
    for (; e < end; e++) {
        int s0 = g_esrc[e];
        uint2 p0 = rows[s0 * 32 + lane];
        float2 f;
        f = __half22float2(*(__half2*)&p0.x); a0 += f.x; a1 += f.y;
        f = __half22float2(*(__half2*)&p0.y); a2 += f.x; a3 += f.y;
    }
    float n2 = g_norm2[w];
    __half2 q0 = __floats2half2_rn(a0 * n2, a1 * n2);
    __half2 q1 = __floats2half2_rn(a2 * n2, a3 * n2);
    uint2 o;
    o.x = *(uint32_t*)&q0;
    o.y = *(uint32_t*)&q1;
    ((uint2*)g_T)[w * 32 + lane] = o;
}

// ---- hop2: Ah[v] = norm[v] * sum T[src] ----
__global__ void gather2_k() {
    int w = (blockIdx.x * blockDim.x + threadIdx.x) >> 5;
    int lane = threadIdx.x & 31;
    if (w >= Nn) return;
    int beg = g_row[w], end = beg + g_deg[w];
    const uint2* rows = (const uint2*)g_T;
    float a0 = 0.f, a1 = 0.f, a2 = 0.f, a3 = 0.f;
    int e = beg;
    for (; e + 3 < end; e += 4) {
        int s0 = g_esrc[e], s1 = g_esrc[e + 1], s2 = g_esrc[e + 2], s3 = g_esrc[e + 3];
        uint2 p0 = rows[s0 * 32 + lane], p1 = rows[s1 * 32 + lane];
        uint2 p2 = rows[s2 * 32 + lane], p3 = rows[s3 * 32 + lane];
        float2 f;
        f = __half22float2(*(__half2*)&p0.x); a0 += f.x; a1 += f.y;
        f = __half22float2(*(__half2*)&p0.y); a2 += f.x; a3 += f.y;
        f = __half22float2(*(__half2*)&p1.x); a0 += f.x; a1 += f.y;
        f = __half22float2(*(__half2*)&p1.y); a2 += f.x; a3 += f.y;
        f = __half22float2(*(__half2*)&p2.x); a0 += f.x; a1 += f.y;
        f = __half22float2(*(__half2*)&p2.y); a2 += f.x; a3 += f.y;
        f = __half22float2(*(__half2*)&p3.x); a0 += f.x; a1 += f.y;
        f = __half22float2(*(__half2*)&p3.y); a2 += f.x; a3 += f.y;
    }
    for (; e < end; e++) {
        int s0 = g_esrc[e];
        uint2 p0 = rows[s0 * 32 + lane];
        float2 f;
        f = __half22float2(*(__half2*)&p0.x); a0 += f.x; a1 += f.y;
        f = __half22float2(*(__half2*)&p0.y); a2 += f.x; a3 += f.y;
    }
    float nw = g_norm[w];
    __half2 q0 = __floats2half2_rn(a0 * nw, a1 * nw);
    __half2 q1 = __floats2half2_rn(a2 * nw, a3 * nw);
    uint2 o;
    o.x = *(uint32_t*)&q0;
    o.y = *(uint32_t*)&q1;
    ((uint2*)g_Ah)[w * 32 + lane] = o;
}

// ---------------- fused GEMM1+GEMM2 via fp16 mma.sync (1-pass) ----------------
#define SA   0                   // 128 x 272B = 34816
#define SB   34816               // 128 x 272B = 34816
#define SW2  69632               // 48*264*2 = 25344
#define SM_TOT 94976

__device__ __forceinline__ uint32_t smem_u32(const void* p) {
    uint32_t a;
    asm("{ .reg .u64 t; cvta.to.shared.u64 t, %1; cvt.u32.u64 %0, t; }" : "=r"(a) : "l"(p));
    return a;
}
#define LDSM4(R, addr) \
    asm volatile("ldmatrix.sync.aligned.m8n8.x4.shared.b16 {%0,%1,%2,%3}, [%4];" \
        : "=r"((R)[0]), "=r"((R)[1]), "=r"((R)[2]), "=r"((R)[3]) : "r"(addr))
#define MMAF16(C, A, B0, B1) \
    asm volatile("mma.sync.aligned.m16n8k16.row.col.f32.f16.f16.f32 " \
        "{%0,%1,%2,%3},{%4,%5,%6,%7},{%8,%9},{%0,%1,%2,%3};" \
        : "+f"((C)[0]), "+f"((C)[1]), "+f"((C)[2]), "+f"((C)[3]) \
        : "r"((A)[0]), "r"((A)[1]), "r"((A)[2]), "r"((A)[3]), "r"(B0), "r"(B1))

__device__ __forceinline__ uint32_t packh2(float a, float b) {
    __half2 h = __floats2half2_rn(a, b);
    return *(uint32_t*)&h;
}

__global__ void __launch_bounds__(256, 2) gemm1_fused(const float* __restrict__ b1) {
    extern __shared__ char sm[];
    int tid = threadIdx.x;
    int m0 = blockIdx.x * 128, n0 = blockIdx.y * 128;

    // ---- copy A (pre-converted fp16, pure bulk copy) ----
    {
        const uint4* sA = (const uint4*)(g_Ah + (size_t)m0 * INF);
#pragma unroll
        for (int i = 0; i < 8; i++) {
            int idx = tid + i * 256;            // 0..2047 uint4
            int row = idx >> 4, c = idx & 15;
            *(uint4*)(sm + SA + row * 272 + c * 16) = sA[idx];
        }
    }
    // ---- copy B (W1^T) tile ----
    {
        int nn = tid >> 1, half = tid & 1;
        const uint4* sBg = (const uint4*)&g_Bh[(n0 + nn) * INF + half * 64];
        uint4* dB = (uint4*)(sm + SB + nn * 272 + half * 128);
#pragma unroll
        for (int i = 0; i < 8; i++) dB[i] = sBg[i];
    }
    // ---- copy W2^T ----
    {
        const uint4* sh = (const uint4*)g_W2h;
        uint4* dh = (uint4*)(sm + SW2);
#pragma unroll
        for (int i = 0; i < 7; i++) {
            int idx = tid + i * 256;
            if (idx < (W2N * W2LD * 2) / 16) dh[idx] = sh[idx];
        }
    }
    __syncthreads();

    int lane = tid & 31, w = tid >> 5;
    int wm = (w & 3) * 32, wn = (w >> 2) * 64;
    uint32_t sb = smem_u32(sm);

    uint32_t aRow = (uint32_t)(wm + (lane & 15));
    uint32_t aK   = (uint32_t)((lane >> 4) * 8);
    uint32_t aOff = sb + SA + aRow * 272 + aK * 2;
    uint32_t bRow = (uint32_t)(wn + (lane & 7) + ((lane >> 4) & 1) * 8);
    uint32_t bK   = (uint32_t)(((lane >> 3) & 1) * 8);
    uint32_t bOff = sb + SB + bRow * 272 + bK * 2;

    float acc[2][8][4];
#pragma unroll
    for (int a = 0; a < 2; a++)
#pragma unroll
        for (int b = 0; b < 8; b++)
#pragma unroll
            for (int c = 0; c < 4; c++) acc[a][b][c] = 0.f;

#pragma unroll
    for (int ks = 0; ks < 8; ks++) {
        uint32_t k2 = (uint32_t)(ks * 32);
        uint32_t Aa[2][4], Bb[4][4];
        LDSM4(Aa[0], aOff + k2);
        LDSM4(Aa[1], aOff + k2 + 16 * 272);
#pragma unroll
        for (int p = 0; p < 4; p++)
            LDSM4(Bb[p], bOff + k2 + p * 16 * 272);
#pragma unroll
        for (int mf = 0; mf < 2; mf++) {
#pragma unroll
            for (int nf = 0; nf < 8; nf++) {
                int p = nf >> 1, s = (nf & 1) * 2;
                MMAF16(acc[mf][nf], Aa[mf], Bb[p][s], Bb[p][s + 1]);
            }
        }
    }

    // ---- bias + relu in registers ----
    int t = lane & 3;
#pragma unroll
    for (int nf = 0; nf < 8; nf++) {
        int col = n0 + wn + nf * 8 + t * 2;
        float2 bb = *(const float2*)&b1[col];
#pragma unroll
        for (int mf = 0; mf < 2; mf++) {
            acc[mf][nf][0] = fmaxf(acc[mf][nf][0] + bb.x, 0.f);
            acc[mf][nf][1] = fmaxf(acc[mf][nf][1] + bb.y, 0.f);
            acc[mf][nf][2] = fmaxf(acc[mf][nf][2] + bb.x, 0.f);
            acc[mf][nf][3] = fmaxf(acc[mf][nf][3] + bb.y, 0.f);
        }
    }

    // ---- gemm2: z(fp16) @ W2, k-slice = warp's 64 cols ----
    float oacc[2][5][4];
#pragma unroll
    for (int a = 0; a < 2; a++)
#pragma unroll
        for (int b = 0; b < 5; b++)
#pragma unroll
            for (int c = 0; c < 4; c++) oacc[a][b][c] = 0.f;

    uint32_t w2row = (uint32_t)((lane & 7) + ((lane >> 4) & 1) * 8);
    uint32_t w2kh  = (uint32_t)(((lane >> 3) & 1) * 16);
    uint32_t w2base = sb + SW2 + w2row * (W2LD * 2) + w2kh;

#pragma unroll
    for (int c = 0; c < 4; c++) {
        uint32_t kb = (uint32_t)((n0 + wn + 16 * c) * 2);
        uint32_t Bq[3][4];
#pragma unroll
        for (int p = 0; p < 3; p++)
            LDSM4(Bq[p], w2base + p * 16 * (W2LD * 2) + kb);
#pragma unroll
        for (int mf = 0; mf < 2; mf++) {
            uint32_t za[4];
            za[0] = packh2(acc[mf][2 * c][0],     acc[mf][2 * c][1]);
            za[1] = packh2(acc[mf][2 * c][2],     acc[mf][2 * c][3]);
            za[2] = packh2(acc[mf][2 * c + 1][0], acc[mf][2 * c + 1][1]);
            za[3] = packh2(acc[mf][2 * c + 1][2], acc[mf][2 * c + 1][3]);
#pragma unroll
            for (int o = 0; o < 5; o++) {
                int p = o >> 1, s = (o & 1) * 2;
                MMAF16(oacc[mf][o], za, Bq[p][s], Bq[p][s + 1]);
            }
        }
    }

    // ---- write partials ----
    int bufid = blockIdx.y * 2 + (w >> 2);
    int g = lane >> 2;
    float* part = g_part[bufid];
#pragma unroll
    for (int mf = 0; mf < 2; mf++) {
        int r0 = m0 + wm + mf * 16 + g;
        int r1 = r0 + 8;
#pragma unroll
        for (int o = 0; o < 5; o++) {
            int col = o * 8 + t * 2;
            if (r0 < Nn) *(float2*)&part[(size_t)r0 * CLSF + col] =
                make_float2(oacc[mf][o][0], oacc[mf][o][1]);
            if (r1 < Nn) *(float2*)&part[(size_t)r1 * CLSF + col] =
                make_float2(oacc[mf][o][2], oacc[mf][o][3]);
        }
    }
}

// ---------------- combine: out = sum(parts) + b2 ----------------
__global__ void combine_k(const float* __restrict__ b2, float* __restrict__ out) {
    int i = blockIdx.x * 256 + threadIdx.x;      // float2 index
    if (i >= Nn * CLSF / 2) return;
    const float2* p0 = (const float2*)g_part[0];
    const float2* p1 = (const float2*)g_part[1];
    const float2* p2 = (const float2*)g_part[2];
    const float2* p3 = (const float2*)g_part[3];
    float2 a = p0[i], b = p1[i], c = p2[i], d = p3[i];
    int col2 = i % (CLSF / 2);
    float2 bb = *(const float2*)&b2[col2 * 2];
    float2 o;
    o.x = a.x + b.x + c.x + d.x + bb.x;
    o.y = a.y + b.y + c.y + d.y + bb.y;
    ((float2*)out)[i] = o;
}

extern "C" void kernel_launch(void* const* d_in, const int* in_sizes, int n_in,
                              void* d_out, int out_size) {
    const float* features = (const float*)d_in[0];
    const int*   src      = (const int*)d_in[1];
    const int*   dst      = (const int*)d_in[2];
    const float* W1       = (const float*)d_in[3];
    const float* b1       = (const float*)d_in[4];
    const float* W2       = (const float*)d_in[5];
    const float* b2       = (const float*)d_in[6];
    float*       out      = (float*)d_out;

    cudaFuncSetAttribute(gemm1_fused, cudaFuncAttributeMaxDynamicSharedMemorySize, SM_TOT);

    init_k<<<SBLK, 256>>>(W1, W2);
    hist_k<<<(Ee + 255) / 256, 256>>>(dst);
    bsum_k<<<SBLK, 256>>>();
    bscan_k<<<1, 256>>>();
    fill_k<<<SBLK, 256>>>();
    prepX_k<<<(Nn * 32 + 255) / 256, 256>>>((const float4*)features);
    permute_k<<<(Ee + 255) / 256, 256>>>(src, dst);

    gather1_k<<<Nn / 8, 256>>>();
    gather2_k<<<Nn / 8, 256>>>();

    gemm1_fused<<<dim3(MTILES, 2), 256, SM_TOT>>>(b1);
    combine_k<<<(Nn * CLSF / 2 + 255) / 256, 256>>>(b2, out);
}